// round 13
// baseline (speedup 1.0000x reference)
#include <cuda_runtime.h>
#include <cuda_bf16.h>
#include <cstdint>

// ---------------- problem constants ----------------
#define BATCH   4
#define SEQL    2048
#define DM      1024
#define DI      2048
#define NH      64
#define HP      32
#define DS      128
#define DCONV   4
#define CONVD   2304            // DI + 2*DS
#define DPROJ   4416            // 2*DI + 2*DS + NH
#define NL      4
#define ROWS    (BATCH*SEQL)    // 8192
#define DT_OFF  (DI + CONVD)    // 4352
#define NPAD_IN 4480            // DPROJ padded to 128 multiple

// ---------------- device scratch (no allocation allowed) ----------------
__device__ float g_h  [(size_t)ROWS * DM];
__device__ float g_zx [(size_t)ROWS * DPROJ];
__device__ float g_xbc[(size_t)ROWS * CONVD];
__device__ float2 g_dd[(size_t)ROWS * NH];     // (dt, dA) packed
__device__ float g_y  [(size_t)ROWS * DI];     // scan partial (states 0-63) + D*x
__device__ float g_y2 [(size_t)ROWS * DI];     // scan partial (states 64-127)
// bf16 hi/lo GEMM operands
__device__ __nv_bfloat16 g_ah[(size_t)ROWS * DI];
__device__ __nv_bfloat16 g_al[(size_t)ROWS * DI];
__device__ __nv_bfloat16 g_bh[(size_t)NPAD_IN * 1024];
__device__ __nv_bfloat16 g_bl[(size_t)NPAD_IN * 1024];

// ---------------- small helpers ----------------
__device__ __forceinline__ float silu_f(float v) { return v / (1.0f + expf(-v)); }

__device__ __forceinline__ float block_reduce_sum(float v) {
    __shared__ float red[32];
    int lane = threadIdx.x & 31, wid = threadIdx.x >> 5;
#pragma unroll
    for (int o = 16; o; o >>= 1) v += __shfl_xor_sync(0xffffffffu, v, o);
    if (lane == 0) red[wid] = v;
    __syncthreads();
    float t = (threadIdx.x < (blockDim.x >> 5)) ? red[threadIdx.x] : 0.f;
    if (wid == 0) {
#pragma unroll
        for (int o = 16; o; o >>= 1) t += __shfl_xor_sync(0xffffffffu, t, o);
        if (lane == 0) red[0] = t;
    }
    __syncthreads();
    return red[0];
}

// ---------------- PTX wrappers (sm_100-baseline safe) ----------------
__device__ __forceinline__ uint32_t smem_u32(const void* p) {
    uint32_t a;
    asm("{ .reg .u64 t; cvta.to.shared.u64 t, %1; cvt.u32.u64 %0, t; }" : "=r"(a) : "l"(p));
    return a;
}
__device__ __forceinline__ void cp_async16(uint32_t dst, const void* src) {
    asm volatile("cp.async.cg.shared.global [%0], [%1], 16;" :: "r"(dst), "l"(src));
}
__device__ __forceinline__ void cp_async8(uint32_t dst, const void* src) {
    asm volatile("cp.async.ca.shared.global [%0], [%1], 8;" :: "r"(dst), "l"(src));
}
__device__ __forceinline__ void cp_commit() { asm volatile("cp.async.commit_group;" ::: "memory"); }
__device__ __forceinline__ void cp_wait0()  { asm volatile("cp.async.wait_group 0;" ::: "memory"); }
__device__ __forceinline__ void cp_wait1()  { asm volatile("cp.async.wait_group 1;" ::: "memory"); }

__device__ __forceinline__ void ldm_x4(uint32_t& r0, uint32_t& r1, uint32_t& r2, uint32_t& r3,
                                       uint32_t addr) {
    asm volatile("ldmatrix.sync.aligned.m8n8.x4.shared.b16 {%0,%1,%2,%3}, [%4];"
                 : "=r"(r0), "=r"(r1), "=r"(r2), "=r"(r3) : "r"(addr));
}
__device__ __forceinline__ void mma_bf16(float* c, const uint32_t* a, const uint32_t* b) {
    asm volatile("mma.sync.aligned.m16n8k16.row.col.f32.bf16.bf16.f32 "
                 "{%0,%1,%2,%3}, {%4,%5,%6,%7}, {%8,%9}, {%0,%1,%2,%3};"
                 : "+f"(c[0]), "+f"(c[1]), "+f"(c[2]), "+f"(c[3])
                 : "r"(a[0]), "r"(a[1]), "r"(a[2]), "r"(a[3]), "r"(b[0]), "r"(b[1]));
}

// ---------------- bf16 triple-pass GEMM, 2-stage, 2 CTAs/SM (R10 best) -------------
#define LDS 40
#define TILEB (128 * LDS * 2)
#define STAGEB (4 * TILEB)
#define GEMM_SMEM (2 * STAGEB)               // 81920 B -> 2 CTAs/SM

__global__ void __launch_bounds__(256, 2)
gemm3_kernel(const __nv_bfloat16* __restrict__ Ah, const __nv_bfloat16* __restrict__ Al,
             const __nv_bfloat16* __restrict__ Bh, const __nv_bfloat16* __restrict__ Bl,
             const float* __restrict__ Cadd, float* __restrict__ C, int N, int K)
{
    extern __shared__ char smem[];
    const uint32_t sb = smem_u32(smem);
    const int tid = threadIdx.x;
    const int lane = tid & 31, wid = tid >> 5;
    const int wm = wid >> 1, wn = wid & 1;
    const size_t m0 = (size_t)blockIdx.y * 128;
    const size_t n0 = (size_t)blockIdx.x * 128;
    const int KC = K >> 5;

    float acc[2][8][4];
#pragma unroll
    for (int i = 0; i < 2; i++)
#pragma unroll
        for (int j = 0; j < 8; j++)
#pragma unroll
            for (int q = 0; q < 4; q++) acc[i][j][q] = 0.f;

    const __nv_bfloat16* gbase[4] = { Ah, Al, Bh, Bl };
    const int amr = lane & 15, akc = (lane >> 4) << 3;
    const int bnr = (lane & 7) + ((lane >> 4) << 3), bkc = ((lane >> 3) & 1) << 3;

    auto load_stage = [&](int kc, int st) {
        size_t kOff = (size_t)kc << 5;
#pragma unroll
        for (int j = 0; j < 8; j++) {
            int i = tid + (j << 8);
            int t = i >> 9, r = (i >> 2) & 127, c = i & 3;
            size_t row = (t < 2) ? (m0 + r) : (n0 + r);
            const __nv_bfloat16* g = gbase[t] + row * (size_t)K + kOff + (c << 3);
            uint32_t d = sb + st * STAGEB + (uint32_t)t * TILEB + (uint32_t)(r * LDS + (c << 3)) * 2;
            cp_async16(d, g);
        }
        cp_commit();
    };

    load_stage(0, 0);

    for (int kc = 0; kc < KC; kc++) {
        int st = kc & 1;
        if (kc + 1 < KC) { load_stage(kc + 1, st ^ 1); cp_wait1(); }
        else             { cp_wait0(); }
        __syncthreads();

        uint32_t sA = sb + st * STAGEB;
        uint32_t sAh = sA;
        uint32_t sAl = sA + TILEB;
        uint32_t sBh = sA + 2 * TILEB;
        uint32_t sBl = sA + 3 * TILEB;

#pragma unroll
        for (int kk = 0; kk < 2; kk++) {
            uint32_t ah[2][4], al[2][4];
#pragma unroll
            for (int mt = 0; mt < 2; mt++) {
                uint32_t off = (uint32_t)((wm * 32 + mt * 16 + amr) * LDS + kk * 16 + akc) * 2;
                ldm_x4(ah[mt][0], ah[mt][1], ah[mt][2], ah[mt][3], sAh + off);
                ldm_x4(al[mt][0], al[mt][1], al[mt][2], al[mt][3], sAl + off);
            }
#pragma unroll
            for (int nt2 = 0; nt2 < 4; nt2++) {
                uint32_t off = (uint32_t)((wn * 64 + nt2 * 16 + bnr) * LDS + kk * 16 + bkc) * 2;
                uint32_t bh0[2], bh1[2], bl0[2], bl1[2];
                ldm_x4(bh0[0], bh0[1], bh1[0], bh1[1], sBh + off);
                ldm_x4(bl0[0], bl0[1], bl1[0], bl1[1], sBl + off);
                mma_bf16(acc[0][nt2 * 2],     ah[0], bh0);
                mma_bf16(acc[0][nt2 * 2 + 1], ah[0], bh1);
                mma_bf16(acc[1][nt2 * 2],     ah[1], bh0);
                mma_bf16(acc[1][nt2 * 2 + 1], ah[1], bh1);
                mma_bf16(acc[0][nt2 * 2],     ah[0], bl0);
                mma_bf16(acc[0][nt2 * 2 + 1], ah[0], bl1);
                mma_bf16(acc[1][nt2 * 2],     ah[1], bl0);
                mma_bf16(acc[1][nt2 * 2 + 1], ah[1], bl1);
                mma_bf16(acc[0][nt2 * 2],     al[0], bh0);
                mma_bf16(acc[0][nt2 * 2 + 1], al[0], bh1);
                mma_bf16(acc[1][nt2 * 2],     al[1], bh0);
                mma_bf16(acc[1][nt2 * 2 + 1], al[1], bh1);
            }
        }
        __syncthreads();
    }

    const int colb = (lane & 3) << 1;
    const int rowb = lane >> 2;
#pragma unroll
    for (int mt = 0; mt < 2; mt++) {
        size_t r0 = m0 + wm * 32 + mt * 16 + rowb;
#pragma unroll
        for (int half = 0; half < 2; half++) {
            size_t r = r0 + half * 8;
            float* crow = C + r * (size_t)N;
            const float* arow = Cadd ? Cadd + r * (size_t)N : nullptr;
#pragma unroll
            for (int nt = 0; nt < 8; nt++) {
                int col = (int)n0 + wn * 64 + nt * 8 + colb;
                if (col < N) {
                    float2 v;
                    v.x = acc[mt][nt][half * 2 + 0];
                    v.y = acc[mt][nt][half * 2 + 1];
                    if (arow) { v.x += arow[col]; v.y += arow[col + 1]; }
                    *(float2*)(crow + col) = v;
                }
            }
        }
    }
}

// ---------------- elementwise / norm kernels ----------------
__global__ void rmsnorm_kernel(const float* __restrict__ src, const float* __restrict__ w,
                               float* __restrict__ dst, int D) {
    int row = blockIdx.x;
    const float* s = src + (size_t)row * D;
    float*       d = dst + (size_t)row * D;
    float ss = 0.f;
    for (int i = threadIdx.x * 4; i < D; i += blockDim.x * 4) {
        float4 v = *(const float4*)(s + i);
        ss += v.x * v.x + v.y * v.y + v.z * v.z + v.w * v.w;
    }
    float scale = rsqrtf(block_reduce_sum(ss) / (float)D + 1e-5f);
    for (int i = threadIdx.x * 4; i < D; i += blockDim.x * 4) {
        float4 v = *(const float4*)(s + i);
        float4 wv = *(const float4*)(w + i);
        float4 o;
        o.x = v.x * scale * wv.x; o.y = v.y * scale * wv.y;
        o.z = v.z * scale * wv.z; o.w = v.w * scale * wv.w;
        *(float4*)(d + i) = o;
    }
}

__global__ void rmsnorm_split_kernel(const float* __restrict__ src, const float* __restrict__ w,
                                     __nv_bfloat16* __restrict__ hi, __nv_bfloat16* __restrict__ lo,
                                     int D) {
    int row = blockIdx.x;
    const float* s = src + (size_t)row * D;
    float ss = 0.f;
    for (int i = threadIdx.x * 4; i < D; i += blockDim.x * 4) {
        float4 v = *(const float4*)(s + i);
        ss += v.x * v.x + v.y * v.y + v.z * v.z + v.w * v.w;
    }
    float scale = rsqrtf(block_reduce_sum(ss) / (float)D + 1e-5f);
    for (int i = threadIdx.x * 4; i < D; i += blockDim.x * 4) {
        float4 v = *(const float4*)(s + i);
        float4 wv = *(const float4*)(w + i);
        float o[4] = { v.x * scale * wv.x, v.y * scale * wv.y,
                       v.z * scale * wv.z, v.w * scale * wv.w };
        __nv_bfloat16 h[4], l[4];
#pragma unroll
        for (int q = 0; q < 4; q++) {
            h[q] = __float2bfloat16(o[q]);
            l[q] = __float2bfloat16(o[q] - __bfloat162float(h[q]));
        }
        *(__nv_bfloat162*)(hi + (size_t)row * D + i)     = __nv_bfloat162(h[0], h[1]);
        *(__nv_bfloat162*)(hi + (size_t)row * D + i + 2) = __nv_bfloat162(h[2], h[3]);
        *(__nv_bfloat162*)(lo + (size_t)row * D + i)     = __nv_bfloat162(l[0], l[1]);
        *(__nv_bfloat162*)(lo + (size_t)row * D + i + 2) = __nv_bfloat162(l[2], l[3]);
    }
}

__global__ void wsplit_kernel(const float* __restrict__ W,
                              __nv_bfloat16* __restrict__ Th, __nv_bfloat16* __restrict__ Tl,
                              int K, int N, int Npad) {
    __shared__ float tile[32][33];
    int nb = blockIdx.x * 32, kb = blockIdx.y * 32;
    int tx = threadIdx.x, ty = threadIdx.y;
#pragma unroll
    for (int j = 0; j < 4; j++) {
        int k = kb + ty + j * 8, n = nb + tx;
        tile[ty + j * 8][tx] = (n < N) ? W[(size_t)k * N + n] : 0.f;
    }
    __syncthreads();
#pragma unroll
    for (int j = 0; j < 4; j++) {
        int n = nb + ty + j * 8, k = kb + tx;
        float v = tile[tx][ty + j * 8];
        __nv_bfloat16 h = __float2bfloat16(v);
        Th[(size_t)n * K + k] = h;
        Tl[(size_t)n * K + k] = __float2bfloat16(v - __bfloat162float(h));
    }
}

// causal depthwise conv1d + SiLU, 4 timesteps per thread (sliding window)
__global__ void conv_silu_kernel(const float* __restrict__ cw, const float* __restrict__ cb) {
    size_t idx = (size_t)blockIdx.x * blockDim.x + threadIdx.x;
    if (idx >= (size_t)(ROWS / 4) * CONVD) return;
    int c = (int)(idx % CONVD);
    size_t r = idx / CONVD;
    int lb = (int)(r % (SEQL / 4));
    size_t b = r / (SEQL / 4);
    int l0 = lb * 4;
    const float* col = g_zx + ((b * SEQL + l0)) * (size_t)DPROJ + DI + c;
    float w0 = cw[c * 4 + 0], w1 = cw[c * 4 + 1], w2 = cw[c * 4 + 2], w3 = cw[c * 4 + 3];
    float cbv = cb[c];
    float v[7];
#pragma unroll
    for (int j = 0; j < 7; j++) {
        int l = l0 + j - 3;
        v[j] = (l >= 0) ? col[(ptrdiff_t)(j - 3) * DPROJ] : 0.f;
    }
    float* out = g_xbc + ((b * SEQL + l0)) * (size_t)CONVD + c;
#pragma unroll
    for (int k = 0; k < 4; k++) {
        float acc = cbv + v[k] * w0 + v[k + 1] * w1 + v[k + 2] * w2 + v[k + 3] * w3;
        out[(size_t)k * CONVD] = silu_f(acc);
    }
}

// dt = softplus(raw + bias); dA = exp(dt*A). packed as float2
__global__ void dt_kernel(const float* __restrict__ dtb, const float* __restrict__ Alog) {
    int idx = blockIdx.x * blockDim.x + threadIdx.x;
    if (idx >= ROWS * NH) return;
    int h = idx & (NH - 1);
    int bl = idx >> 6;
    float x = g_zx[(size_t)bl * DPROJ + DT_OFF + h] + dtb[h];
    float sp = (x > 20.f) ? x : log1pf(expf(x));
    g_dd[idx] = make_float2(sp, expf(sp * (-expf(Alog[h]))));
}

// ---------------- state-split selective scan ----------------
// 2 CTAs per (b,h): blockIdx.x = half (states half*64 .. half*64+63)
// 256 threads, 8 warps x 8 states, lane = p. Partial y -> g_y (half 0, + D*x) / g_y2.
#define SCHUNK 32
#define SC_BFL2 (SCHUNK * 64)                // 2048 floats per B (or C) buffer
#define SC_XFL (SCHUNK * 32)                 // 1024
#define SCAN_SMEM ((2*SC_BFL2*2 + 2*SC_XFL + 2*SCHUNK*2 + SCHUNK*256) * 4)  // 74240 B

__global__ void __launch_bounds__(256) scan_kernel(const float* __restrict__ Dv) {
    extern __shared__ float ss[];
    float* sB = ss;                           // [2][32][64]
    float* sC = sB + 2 * SC_BFL2;             // [2][32][64]
    float* sX = sC + 2 * SC_BFL2;             // [2][32][32]
    float* sD = sX + 2 * SC_XFL;              // [2][32] float2
    float* sP = sD + 2 * SCHUNK * 2;          // [32][256]

    const uint32_t aB = smem_u32(sB), aC = smem_u32(sC), aX = smem_u32(sX), aD = smem_u32(sD);

    int half = blockIdx.x;
    int bh = blockIdx.y;
    int b = bh >> 6, h = bh & 63;
    int tid = threadIdx.x;
    int w = tid >> 5, lane = tid & 31;
    int nbase = half * 64;                    // this CTA's state offset

    float s[8];
#pragma unroll
    for (int i = 0; i < 8; i++) s[i] = 0.f;

    float Dh = Dv[h];
    const float*  xb  = g_xbc + (size_t)b * SEQL * CONVD;
    const float2* pdd = g_dd  + (size_t)b * SEQL * NH + h;
    float*        yb  = (half ? g_y2 : g_y) + (size_t)b * SEQL * DI + h * HP;

    auto load_chunk = [&](int c, int buf) {
        const float* base = xb + (size_t)c * SCHUNK * CONVD;
        // B and C halves: 32 rows x 256B each -> 512 chunks per tensor -> 2/thread
#pragma unroll
        for (int jj = 0; jj < 2; jj++) {
            int i = tid + (jj << 8);
            int t = i >> 4, cc = i & 15;
            const float* src = base + (size_t)t * CONVD + DI + nbase + cc * 4;
            cp_async16(aB + (uint32_t)(buf * SC_BFL2 + t * 64 + cc * 4) * 4, src);
            cp_async16(aC + (uint32_t)(buf * SC_BFL2 + t * 64 + cc * 4) * 4, src + DS);
        }
        {
            int t = tid >> 3, cc = tid & 7;
            cp_async16(aX + (uint32_t)(buf * SC_XFL + t * 32 + cc * 4) * 4,
                       base + (size_t)t * CONVD + h * HP + cc * 4);
        }
        if (tid < SCHUNK)
            cp_async8(aD + (uint32_t)(buf * SCHUNK + tid) * 8,
                      pdd + ((size_t)c * SCHUNK + tid) * NH);
        cp_commit();
    };

    const int NCH = SEQL / SCHUNK;
    load_chunk(0, 0);

    int buf = 0;
    for (int c = 0; c < NCH; c++) {
        if (c + 1 < NCH) { load_chunk(c + 1, buf ^ 1); cp_wait1(); }
        else             { cp_wait0(); }
        __syncthreads();

        const float*  pB = sB + buf * SC_BFL2 + w * 8;
        const float*  pC = sC + buf * SC_BFL2 + w * 8;
        const float*  pX = sX + buf * SC_XFL;
        const float2* pD = (const float2*)(sD + buf * SCHUNK * 2);

#pragma unroll 2
        for (int tt = 0; tt < SCHUNK; tt++) {
            float2 dd = pD[tt];
            float xv = pX[tt * 32 + lane];
            float Bv[8], Cv[8];
            ((float4*)Bv)[0] = *(const float4*)(pB + tt * 64);
            ((float4*)Bv)[1] = *(const float4*)(pB + tt * 64 + 4);
            ((float4*)Cv)[0] = *(const float4*)(pC + tt * 64);
            ((float4*)Cv)[1] = *(const float4*)(pC + tt * 64 + 4);
            float dtx = dd.x * xv;
            float a0 = 0.f, a1 = 0.f;
#pragma unroll
            for (int i = 0; i < 8; i += 2) {
                s[i]   = fmaf(s[i],   dd.y, dtx * Bv[i]);
                s[i+1] = fmaf(s[i+1], dd.y, dtx * Bv[i+1]);
                a0 = fmaf(s[i],   Cv[i],   a0);
                a1 = fmaf(s[i+1], Cv[i+1], a1);
            }
            sP[tt * 256 + tid] = a0 + a1;
        }
        __syncthreads();

        size_t tg = (size_t)c * SCHUNK;
#pragma unroll
        for (int q = 0; q < 4; q++) {
            int idx = q * 256 + tid;
            int tt = idx >> 5, p = idx & 31;
            const float* pp = sP + tt * 256 + p;
            float y = pp[0] + pp[32] + pp[64] + pp[96] +
                      pp[128] + pp[160] + pp[192] + pp[224];
            if (half == 0) {
                float xv = sX[buf * SC_XFL + tt * 32 + p];
                y = fmaf(Dh, xv, y);
            }
            yb[(tg + tt) * DI + p] = y;
        }
        __syncthreads();
        buf ^= 1;
    }
}

// y' = rmsnorm((y1+y2) * silu(z)) * gw -> bf16 hi/lo (A operand of out_proj)
__global__ void gate_norm_split_kernel(const float* __restrict__ gw,
                                       __nv_bfloat16* __restrict__ hi,
                                       __nv_bfloat16* __restrict__ lo) {
    int row = blockIdx.x;
    const float* yr  = g_y  + (size_t)row * DI;
    const float* y2r = g_y2 + (size_t)row * DI;
    const float* zr  = g_zx + (size_t)row * DPROJ;
    int base = threadIdx.x * 8;
    float v[8];
    float ss = 0.f;
#pragma unroll
    for (int i = 0; i < 8; i++) {
        float g = (yr[base + i] + y2r[base + i]) * silu_f(zr[base + i]);
        v[i] = g;
        ss += g * g;
    }
    float scale = rsqrtf(block_reduce_sum(ss) / (float)DI + 1e-5f);
    __nv_bfloat16 h[8], l[8];
#pragma unroll
    for (int i = 0; i < 8; i++) {
        float o = v[i] * scale * gw[base + i];
        h[i] = __float2bfloat16(o);
        l[i] = __float2bfloat16(o - __bfloat162float(h[i]));
    }
#pragma unroll
    for (int i = 0; i < 4; i++) {
        *(__nv_bfloat162*)(hi + (size_t)row * DI + base + i * 2) = __nv_bfloat162(h[i * 2], h[i * 2 + 1]);
        *(__nv_bfloat162*)(lo + (size_t)row * DI + base + i * 2) = __nv_bfloat162(l[i * 2], l[i * 2 + 1]);
    }
}

// ---------------- launch ----------------
extern "C" void kernel_launch(void* const* d_in, const int* in_sizes, int n_in,
                              void* d_out, int out_size) {
    const float* x        = (const float*)d_in[0];
    const float* W_in     = (const float*)d_in[1];
    const float* conv_w   = (const float*)d_in[2];
    const float* conv_b   = (const float*)d_in[3];
    const float* dt_bias  = (const float*)d_in[4];
    const float* A_log    = (const float*)d_in[5];
    const float* Dvec     = (const float*)d_in[6];
    const float* gate_w   = (const float*)d_in[7];
    const float* W_out    = (const float*)d_in[8];
    const float* block_w  = (const float*)d_in[9];
    const float* final_w  = (const float*)d_in[10];

    float *ph, *pzx;
    __nv_bfloat16 *pah, *pal, *pbh, *pbl;
    cudaGetSymbolAddress((void**)&ph,  g_h);
    cudaGetSymbolAddress((void**)&pzx, g_zx);
    cudaGetSymbolAddress((void**)&pah, g_ah);
    cudaGetSymbolAddress((void**)&pal, g_al);
    cudaGetSymbolAddress((void**)&pbh, g_bh);
    cudaGetSymbolAddress((void**)&pbl, g_bl);

    cudaFuncSetAttribute(gemm3_kernel, cudaFuncAttributeMaxDynamicSharedMemorySize, GEMM_SMEM);
    cudaFuncSetAttribute(scan_kernel, cudaFuncAttributeMaxDynamicSharedMemorySize, SCAN_SMEM);

    for (int l = 0; l < NL; l++) {
        const float* hsrc = (l == 0) ? x : ph;   // layer 0 reads input directly (no copy)
        rmsnorm_split_kernel<<<ROWS, 256>>>(hsrc, block_w + (size_t)l * DM, pah, pal, DM);
        wsplit_kernel<<<dim3(NPAD_IN / 32, DM / 32), dim3(32, 8)>>>(
            W_in + (size_t)l * DM * DPROJ, pbh, pbl, DM, DPROJ, NPAD_IN);
        gemm3_kernel<<<dim3(NPAD_IN / 128, ROWS / 128), 256, GEMM_SMEM>>>(
            pah, pal, pbh, pbl, nullptr, pzx, DPROJ, DM);

        {
            size_t n = (size_t)(ROWS / 4) * CONVD;
            conv_silu_kernel<<<(unsigned)((n + 255) / 256), 256>>>(
                conv_w + (size_t)l * CONVD * DCONV, conv_b + (size_t)l * CONVD);
        }
        dt_kernel<<<(ROWS * NH + 255) / 256, 256>>>(dt_bias + (size_t)l * NH,
                                                    A_log + (size_t)l * NH);
        scan_kernel<<<dim3(2, BATCH * NH), 256, SCAN_SMEM>>>(Dvec + (size_t)l * NH);
        gate_norm_split_kernel<<<ROWS, 256>>>(gate_w + (size_t)l * DI, pah, pal);

        wsplit_kernel<<<dim3(DM / 32, DI / 32), dim3(32, 8)>>>(
            W_out + (size_t)l * DI * DM, pbh, pbl, DI, DM, DM);
        gemm3_kernel<<<dim3(DM / 128, ROWS / 128), 256, GEMM_SMEM>>>(
            pah, pal, pbh, pbl, hsrc, ph, DM, DI);
    }

    rmsnorm_kernel<<<ROWS, 256>>>(ph, final_w, (float*)d_out, DM);
}

// round 14
// speedup vs baseline: 1.0821x; 1.0821x over previous
#include <cuda_runtime.h>
#include <cuda_bf16.h>
#include <cstdint>

// ---------------- problem constants ----------------
#define BATCH   4
#define SEQL    2048
#define DM      1024
#define DI      2048
#define NH      64
#define HP      32
#define DS      128
#define DCONV   4
#define CONVD   2304            // DI + 2*DS
#define DPROJ   4416            // 2*DI + 2*DS + NH
#define NL      4
#define ROWS    (BATCH*SEQL)    // 8192
#define DT_OFF  (DI + CONVD)    // 4352
#define NPAD_IN 4480            // DPROJ padded to 128 multiple

// ---------------- device scratch (no allocation allowed) ----------------
__device__ float g_h  [(size_t)ROWS * DM];
__device__ float g_zx [(size_t)ROWS * DPROJ];
__device__ float g_xbc[(size_t)ROWS * CONVD];
__device__ float2 g_dd[(size_t)ROWS * NH];     // (dt, dA) packed
__device__ float g_y  [(size_t)ROWS * DI];
// bf16 hi/lo GEMM operands
__device__ __nv_bfloat16 g_ah[(size_t)ROWS * DI];
__device__ __nv_bfloat16 g_al[(size_t)ROWS * DI];
__device__ __nv_bfloat16 g_bh[(size_t)NPAD_IN * 1024];
__device__ __nv_bfloat16 g_bl[(size_t)NPAD_IN * 1024];

// ---------------- small helpers ----------------
__device__ __forceinline__ float silu_f(float v) { return v / (1.0f + expf(-v)); }

__device__ __forceinline__ float block_reduce_sum(float v) {
    __shared__ float red[32];
    int lane = threadIdx.x & 31, wid = threadIdx.x >> 5;
#pragma unroll
    for (int o = 16; o; o >>= 1) v += __shfl_xor_sync(0xffffffffu, v, o);
    if (lane == 0) red[wid] = v;
    __syncthreads();
    float t = (threadIdx.x < (blockDim.x >> 5)) ? red[threadIdx.x] : 0.f;
    if (wid == 0) {
#pragma unroll
        for (int o = 16; o; o >>= 1) t += __shfl_xor_sync(0xffffffffu, t, o);
        if (lane == 0) red[0] = t;
    }
    __syncthreads();
    return red[0];
}

// ---------------- PTX wrappers (sm_100-baseline safe) ----------------
__device__ __forceinline__ uint32_t smem_u32(const void* p) {
    uint32_t a;
    asm("{ .reg .u64 t; cvta.to.shared.u64 t, %1; cvt.u32.u64 %0, t; }" : "=r"(a) : "l"(p));
    return a;
}
__device__ __forceinline__ void cp_async16(uint32_t dst, const void* src) {
    asm volatile("cp.async.cg.shared.global [%0], [%1], 16;" :: "r"(dst), "l"(src));
}
__device__ __forceinline__ void cp_async8(uint32_t dst, const void* src) {
    asm volatile("cp.async.ca.shared.global [%0], [%1], 8;" :: "r"(dst), "l"(src));
}
__device__ __forceinline__ void cp_commit() { asm volatile("cp.async.commit_group;" ::: "memory"); }
__device__ __forceinline__ void cp_wait0()  { asm volatile("cp.async.wait_group 0;" ::: "memory"); }
__device__ __forceinline__ void cp_wait1()  { asm volatile("cp.async.wait_group 1;" ::: "memory"); }

__device__ __forceinline__ void ldm_x4(uint32_t& r0, uint32_t& r1, uint32_t& r2, uint32_t& r3,
                                       uint32_t addr) {
    asm volatile("ldmatrix.sync.aligned.m8n8.x4.shared.b16 {%0,%1,%2,%3}, [%4];"
                 : "=r"(r0), "=r"(r1), "=r"(r2), "=r"(r3) : "r"(addr));
}
__device__ __forceinline__ void mma_bf16(float* c, const uint32_t* a, const uint32_t* b) {
    asm volatile("mma.sync.aligned.m16n8k16.row.col.f32.bf16.bf16.f32 "
                 "{%0,%1,%2,%3}, {%4,%5,%6,%7}, {%8,%9}, {%0,%1,%2,%3};"
                 : "+f"(c[0]), "+f"(c[1]), "+f"(c[2]), "+f"(c[3])
                 : "r"(a[0]), "r"(a[1]), "r"(a[2]), "r"(a[3]), "r"(b[0]), "r"(b[1]));
}

// ---------------- bf16 triple-pass GEMM, 2-stage, 2 CTAs/SM (R10 best) -------------
#define LDS 40
#define TILEB (128 * LDS * 2)
#define STAGEB (4 * TILEB)
#define GEMM_SMEM (2 * STAGEB)               // 81920 B -> 2 CTAs/SM

__global__ void __launch_bounds__(256, 2)
gemm3_kernel(const __nv_bfloat16* __restrict__ Ah, const __nv_bfloat16* __restrict__ Al,
             const __nv_bfloat16* __restrict__ Bh, const __nv_bfloat16* __restrict__ Bl,
             const float* __restrict__ Cadd, float* __restrict__ C, int N, int K)
{
    extern __shared__ char smem[];
    const uint32_t sb = smem_u32(smem);
    const int tid = threadIdx.x;
    const int lane = tid & 31, wid = tid >> 5;
    const int wm = wid >> 1, wn = wid & 1;
    const size_t m0 = (size_t)blockIdx.y * 128;
    const size_t n0 = (size_t)blockIdx.x * 128;
    const int KC = K >> 5;

    float acc[2][8][4];
#pragma unroll
    for (int i = 0; i < 2; i++)
#pragma unroll
        for (int j = 0; j < 8; j++)
#pragma unroll
            for (int q = 0; q < 4; q++) acc[i][j][q] = 0.f;

    const __nv_bfloat16* gbase[4] = { Ah, Al, Bh, Bl };
    const int amr = lane & 15, akc = (lane >> 4) << 3;
    const int bnr = (lane & 7) + ((lane >> 4) << 3), bkc = ((lane >> 3) & 1) << 3;

    auto load_stage = [&](int kc, int st) {
        size_t kOff = (size_t)kc << 5;
#pragma unroll
        for (int j = 0; j < 8; j++) {
            int i = tid + (j << 8);
            int t = i >> 9, r = (i >> 2) & 127, c = i & 3;
            size_t row = (t < 2) ? (m0 + r) : (n0 + r);
            const __nv_bfloat16* g = gbase[t] + row * (size_t)K + kOff + (c << 3);
            uint32_t d = sb + st * STAGEB + (uint32_t)t * TILEB + (uint32_t)(r * LDS + (c << 3)) * 2;
            cp_async16(d, g);
        }
        cp_commit();
    };

    load_stage(0, 0);

    for (int kc = 0; kc < KC; kc++) {
        int st = kc & 1;
        if (kc + 1 < KC) { load_stage(kc + 1, st ^ 1); cp_wait1(); }
        else             { cp_wait0(); }
        __syncthreads();

        uint32_t sA = sb + st * STAGEB;
        uint32_t sAh = sA;
        uint32_t sAl = sA + TILEB;
        uint32_t sBh = sA + 2 * TILEB;
        uint32_t sBl = sA + 3 * TILEB;

#pragma unroll
        for (int kk = 0; kk < 2; kk++) {
            uint32_t ah[2][4], al[2][4];
#pragma unroll
            for (int mt = 0; mt < 2; mt++) {
                uint32_t off = (uint32_t)((wm * 32 + mt * 16 + amr) * LDS + kk * 16 + akc) * 2;
                ldm_x4(ah[mt][0], ah[mt][1], ah[mt][2], ah[mt][3], sAh + off);
                ldm_x4(al[mt][0], al[mt][1], al[mt][2], al[mt][3], sAl + off);
            }
#pragma unroll
            for (int nt2 = 0; nt2 < 4; nt2++) {
                uint32_t off = (uint32_t)((wn * 64 + nt2 * 16 + bnr) * LDS + kk * 16 + bkc) * 2;
                uint32_t bh0[2], bh1[2], bl0[2], bl1[2];
                ldm_x4(bh0[0], bh0[1], bh1[0], bh1[1], sBh + off);
                ldm_x4(bl0[0], bl0[1], bl1[0], bl1[1], sBl + off);
                mma_bf16(acc[0][nt2 * 2],     ah[0], bh0);
                mma_bf16(acc[0][nt2 * 2 + 1], ah[0], bh1);
                mma_bf16(acc[1][nt2 * 2],     ah[1], bh0);
                mma_bf16(acc[1][nt2 * 2 + 1], ah[1], bh1);
                mma_bf16(acc[0][nt2 * 2],     ah[0], bl0);
                mma_bf16(acc[0][nt2 * 2 + 1], ah[0], bl1);
                mma_bf16(acc[1][nt2 * 2],     ah[1], bl0);
                mma_bf16(acc[1][nt2 * 2 + 1], ah[1], bl1);
                mma_bf16(acc[0][nt2 * 2],     al[0], bh0);
                mma_bf16(acc[0][nt2 * 2 + 1], al[0], bh1);
                mma_bf16(acc[1][nt2 * 2],     al[1], bh0);
                mma_bf16(acc[1][nt2 * 2 + 1], al[1], bh1);
            }
        }
        __syncthreads();
    }

    const int colb = (lane & 3) << 1;
    const int rowb = lane >> 2;
#pragma unroll
    for (int mt = 0; mt < 2; mt++) {
        size_t r0 = m0 + wm * 32 + mt * 16 + rowb;
#pragma unroll
        for (int half = 0; half < 2; half++) {
            size_t r = r0 + half * 8;
            float* crow = C + r * (size_t)N;
            const float* arow = Cadd ? Cadd + r * (size_t)N : nullptr;
#pragma unroll
            for (int nt = 0; nt < 8; nt++) {
                int col = (int)n0 + wn * 64 + nt * 8 + colb;
                if (col < N) {
                    float2 v;
                    v.x = acc[mt][nt][half * 2 + 0];
                    v.y = acc[mt][nt][half * 2 + 1];
                    if (arow) { v.x += arow[col]; v.y += arow[col + 1]; }
                    *(float2*)(crow + col) = v;
                }
            }
        }
    }
}

// ---------------- elementwise / norm kernels ----------------
__global__ void rmsnorm_kernel(const float* __restrict__ src, const float* __restrict__ w,
                               float* __restrict__ dst, int D) {
    int row = blockIdx.x;
    const float* s = src + (size_t)row * D;
    float*       d = dst + (size_t)row * D;
    float ss = 0.f;
    for (int i = threadIdx.x * 4; i < D; i += blockDim.x * 4) {
        float4 v = *(const float4*)(s + i);
        ss += v.x * v.x + v.y * v.y + v.z * v.z + v.w * v.w;
    }
    float scale = rsqrtf(block_reduce_sum(ss) / (float)D + 1e-5f);
    for (int i = threadIdx.x * 4; i < D; i += blockDim.x * 4) {
        float4 v = *(const float4*)(s + i);
        float4 wv = *(const float4*)(w + i);
        float4 o;
        o.x = v.x * scale * wv.x; o.y = v.y * scale * wv.y;
        o.z = v.z * scale * wv.z; o.w = v.w * scale * wv.w;
        *(float4*)(d + i) = o;
    }
}

__global__ void rmsnorm_split_kernel(const float* __restrict__ src, const float* __restrict__ w,
                                     __nv_bfloat16* __restrict__ hi, __nv_bfloat16* __restrict__ lo,
                                     int D) {
    int row = blockIdx.x;
    const float* s = src + (size_t)row * D;
    float ss = 0.f;
    for (int i = threadIdx.x * 4; i < D; i += blockDim.x * 4) {
        float4 v = *(const float4*)(s + i);
        ss += v.x * v.x + v.y * v.y + v.z * v.z + v.w * v.w;
    }
    float scale = rsqrtf(block_reduce_sum(ss) / (float)D + 1e-5f);
    for (int i = threadIdx.x * 4; i < D; i += blockDim.x * 4) {
        float4 v = *(const float4*)(s + i);
        float4 wv = *(const float4*)(w + i);
        float o[4] = { v.x * scale * wv.x, v.y * scale * wv.y,
                       v.z * scale * wv.z, v.w * scale * wv.w };
        __nv_bfloat16 h[4], l[4];
#pragma unroll
        for (int q = 0; q < 4; q++) {
            h[q] = __float2bfloat16(o[q]);
            l[q] = __float2bfloat16(o[q] - __bfloat162float(h[q]));
        }
        *(__nv_bfloat162*)(hi + (size_t)row * D + i)     = __nv_bfloat162(h[0], h[1]);
        *(__nv_bfloat162*)(hi + (size_t)row * D + i + 2) = __nv_bfloat162(h[2], h[3]);
        *(__nv_bfloat162*)(lo + (size_t)row * D + i)     = __nv_bfloat162(l[0], l[1]);
        *(__nv_bfloat162*)(lo + (size_t)row * D + i + 2) = __nv_bfloat162(l[2], l[3]);
    }
}

__global__ void wsplit_kernel(const float* __restrict__ W,
                              __nv_bfloat16* __restrict__ Th, __nv_bfloat16* __restrict__ Tl,
                              int K, int N, int Npad) {
    __shared__ float tile[32][33];
    int nb = blockIdx.x * 32, kb = blockIdx.y * 32;
    int tx = threadIdx.x, ty = threadIdx.y;
#pragma unroll
    for (int j = 0; j < 4; j++) {
        int k = kb + ty + j * 8, n = nb + tx;
        tile[ty + j * 8][tx] = (n < N) ? W[(size_t)k * N + n] : 0.f;
    }
    __syncthreads();
#pragma unroll
    for (int j = 0; j < 4; j++) {
        int n = nb + ty + j * 8, k = kb + tx;
        float v = tile[tx][ty + j * 8];
        __nv_bfloat16 h = __float2bfloat16(v);
        Th[(size_t)n * K + k] = h;
        Tl[(size_t)n * K + k] = __float2bfloat16(v - __bfloat162float(h));
    }
}

// causal depthwise conv1d + SiLU, 4 timesteps per thread (sliding window)
__global__ void conv_silu_kernel(const float* __restrict__ cw, const float* __restrict__ cb) {
    size_t idx = (size_t)blockIdx.x * blockDim.x + threadIdx.x;
    if (idx >= (size_t)(ROWS / 4) * CONVD) return;
    int c = (int)(idx % CONVD);
    size_t r = idx / CONVD;
    int lb = (int)(r % (SEQL / 4));
    size_t b = r / (SEQL / 4);
    int l0 = lb * 4;
    const float* col = g_zx + ((b * SEQL + l0)) * (size_t)DPROJ + DI + c;
    float w0 = cw[c * 4 + 0], w1 = cw[c * 4 + 1], w2 = cw[c * 4 + 2], w3 = cw[c * 4 + 3];
    float cbv = cb[c];
    float v[7];
#pragma unroll
    for (int j = 0; j < 7; j++) {
        int l = l0 + j - 3;
        v[j] = (l >= 0) ? col[(ptrdiff_t)(j - 3) * DPROJ] : 0.f;
    }
    float* out = g_xbc + ((b * SEQL + l0)) * (size_t)CONVD + c;
#pragma unroll
    for (int k = 0; k < 4; k++) {
        float acc = cbv + v[k] * w0 + v[k + 1] * w1 + v[k + 2] * w2 + v[k + 3] * w3;
        out[(size_t)k * CONVD] = silu_f(acc);
    }
}

// dt = softplus(raw + bias); dA = exp(dt*A). packed as float2
__global__ void dt_kernel(const float* __restrict__ dtb, const float* __restrict__ Alog) {
    int idx = blockIdx.x * blockDim.x + threadIdx.x;
    if (idx >= ROWS * NH) return;
    int h = idx & (NH - 1);
    int bl = idx >> 6;
    float x = g_zx[(size_t)bl * DPROJ + DT_OFF + h] + dtb[h];
    float sp = (x > 20.f) ? x : log1pf(expf(x));
    g_dd[idx] = make_float2(sp, expf(sp * (-expf(Alog[h]))));
}

// ---------------- selective scan: warp=n-chunk, lane=p, deferred reduction (R10) ----
#define SCHUNK 32
#define SC_BFL (SCHUNK * 128)
#define SC_XFL (SCHUNK * 32)
#define SCAN_SMEM ((2*SC_BFL*2 + 2*SC_XFL + 2*SCHUNK*2 + SCHUNK*256) * 4)  // 107008 B

__global__ void __launch_bounds__(256) scan_kernel(const float* __restrict__ Dv) {
    extern __shared__ float ss[];
    float* sB = ss;
    float* sC = sB + 2 * SC_BFL;
    float* sX = sC + 2 * SC_BFL;
    float* sD = sX + 2 * SC_XFL;
    float* sP = sD + 2 * SCHUNK * 2;

    const uint32_t aB = smem_u32(sB), aC = smem_u32(sC), aX = smem_u32(sX), aD = smem_u32(sD);

    int bh = blockIdx.x;
    int b = bh >> 6, h = bh & 63;
    int tid = threadIdx.x;
    int w = tid >> 5, lane = tid & 31;

    float s[16];
#pragma unroll
    for (int i = 0; i < 16; i++) s[i] = 0.f;

    float Dh = Dv[h];
    const float*  xb  = g_xbc + (size_t)b * SEQL * CONVD;
    const float2* pdd = g_dd  + (size_t)b * SEQL * NH + h;
    float*        yb  = g_y   + (size_t)b * SEQL * DI + h * HP;

    auto load_chunk = [&](int c, int buf) {
        const float* base = xb + (size_t)c * SCHUNK * CONVD;
#pragma unroll
        for (int j = 0; j < 4; j++) {
            int i = tid + (j << 8);
            int t = i >> 5, cc = i & 31;
            const float* src = base + (size_t)t * CONVD + DI + cc * 4;
            cp_async16(aB + (uint32_t)(buf * SC_BFL + t * 128 + cc * 4) * 4, src);
            cp_async16(aC + (uint32_t)(buf * SC_BFL + t * 128 + cc * 4) * 4, src + DS);
        }
        {
            int t = tid >> 3, cc = tid & 7;
            cp_async16(aX + (uint32_t)(buf * SC_XFL + t * 32 + cc * 4) * 4,
                       base + (size_t)t * CONVD + h * HP + cc * 4);
        }
        if (tid < SCHUNK)
            cp_async8(aD + (uint32_t)(buf * SCHUNK + tid) * 8,
                      pdd + ((size_t)c * SCHUNK + tid) * NH);
        cp_commit();
    };

    const int NCH = SEQL / SCHUNK;
    load_chunk(0, 0);

    int buf = 0;
    for (int c = 0; c < NCH; c++) {
        if (c + 1 < NCH) { load_chunk(c + 1, buf ^ 1); cp_wait1(); }
        else             { cp_wait0(); }
        __syncthreads();

        const float*  pB = sB + buf * SC_BFL + w * 16;
        const float*  pC = sC + buf * SC_BFL + w * 16;
        const float*  pX = sX + buf * SC_XFL;
        const float2* pD = (const float2*)(sD + buf * SCHUNK * 2);

#pragma unroll 4
        for (int tt = 0; tt < SCHUNK; tt++) {
            float2 dd = pD[tt];
            float xv = pX[tt * 32 + lane];
            float Bv[16], Cv[16];
#pragma unroll
            for (int j = 0; j < 4; j++) {
                ((float4*)Bv)[j] = *(const float4*)(pB + tt * 128 + j * 4);
                ((float4*)Cv)[j] = *(const float4*)(pC + tt * 128 + j * 4);
            }
            float dtx = dd.x * xv;
            float a0 = 0.f, a1 = 0.f;
#pragma unroll
            for (int i = 0; i < 16; i += 2) {
                s[i]   = fmaf(s[i],   dd.y, dtx * Bv[i]);
                s[i+1] = fmaf(s[i+1], dd.y, dtx * Bv[i+1]);
                a0 = fmaf(s[i],   Cv[i],   a0);
                a1 = fmaf(s[i+1], Cv[i+1], a1);
            }
            sP[tt * 256 + tid] = a0 + a1;
        }
        __syncthreads();

        size_t tg = (size_t)c * SCHUNK;
#pragma unroll
        for (int q = 0; q < 4; q++) {
            int idx = q * 256 + tid;
            int tt = idx >> 5, p = idx & 31;
            const float* pp = sP + tt * 256 + p;
            float y = pp[0] + pp[32] + pp[64] + pp[96] +
                      pp[128] + pp[160] + pp[192] + pp[224];
            float xv = sX[buf * SC_XFL + tt * 32 + p];
            yb[(tg + tt) * DI + p] = fmaf(Dh, xv, y);
        }
        __syncthreads();
        buf ^= 1;
    }
}

// y' = rmsnorm(y * silu(z)) * gw -> bf16 hi/lo (A operand of out_proj)
__global__ void gate_norm_split_kernel(const float* __restrict__ gw,
                                       __nv_bfloat16* __restrict__ hi,
                                       __nv_bfloat16* __restrict__ lo) {
    int row = blockIdx.x;
    const float* yr = g_y  + (size_t)row * DI;
    const float* zr = g_zx + (size_t)row * DPROJ;
    int base = threadIdx.x * 8;
    float v[8];
    float ss = 0.f;
#pragma unroll
    for (int i = 0; i < 8; i++) {
        float g = yr[base + i] * silu_f(zr[base + i]);
        v[i] = g;
        ss += g * g;
    }
    float scale = rsqrtf(block_reduce_sum(ss) / (float)DI + 1e-5f);
    __nv_bfloat16 h[8], l[8];
#pragma unroll
    for (int i = 0; i < 8; i++) {
        float o = v[i] * scale * gw[base + i];
        h[i] = __float2bfloat16(o);
        l[i] = __float2bfloat16(o - __bfloat162float(h[i]));
    }
#pragma unroll
    for (int i = 0; i < 4; i++) {
        *(__nv_bfloat162*)(hi + (size_t)row * DI + base + i * 2) = __nv_bfloat162(h[i * 2], h[i * 2 + 1]);
        *(__nv_bfloat162*)(lo + (size_t)row * DI + base + i * 2) = __nv_bfloat162(l[i * 2], l[i * 2 + 1]);
    }
}

// ---------------- launch ----------------
extern "C" void kernel_launch(void* const* d_in, const int* in_sizes, int n_in,
                              void* d_out, int out_size) {
    const float* x        = (const float*)d_in[0];
    const float* W_in     = (const float*)d_in[1];
    const float* conv_w   = (const float*)d_in[2];
    const float* conv_b   = (const float*)d_in[3];
    const float* dt_bias  = (const float*)d_in[4];
    const float* A_log    = (const float*)d_in[5];
    const float* Dvec     = (const float*)d_in[6];
    const float* gate_w   = (const float*)d_in[7];
    const float* W_out    = (const float*)d_in[8];
    const float* block_w  = (const float*)d_in[9];
    const float* final_w  = (const float*)d_in[10];

    float *ph, *pzx;
    __nv_bfloat16 *pah, *pal, *pbh, *pbl;
    cudaGetSymbolAddress((void**)&ph,  g_h);
    cudaGetSymbolAddress((void**)&pzx, g_zx);
    cudaGetSymbolAddress((void**)&pah, g_ah);
    cudaGetSymbolAddress((void**)&pal, g_al);
    cudaGetSymbolAddress((void**)&pbh, g_bh);
    cudaGetSymbolAddress((void**)&pbl, g_bl);

    cudaFuncSetAttribute(gemm3_kernel, cudaFuncAttributeMaxDynamicSharedMemorySize, GEMM_SMEM);
    cudaFuncSetAttribute(scan_kernel, cudaFuncAttributeMaxDynamicSharedMemorySize, SCAN_SMEM);

    for (int l = 0; l < NL; l++) {
        const float* hsrc = (l == 0) ? x : ph;   // layer 0 reads input directly (no copy)
        rmsnorm_split_kernel<<<ROWS, 256>>>(hsrc, block_w + (size_t)l * DM, pah, pal, DM);
        wsplit_kernel<<<dim3(NPAD_IN / 32, DM / 32), dim3(32, 8)>>>(
            W_in + (size_t)l * DM * DPROJ, pbh, pbl, DM, DPROJ, NPAD_IN);
        gemm3_kernel<<<dim3(NPAD_IN / 128, ROWS / 128), 256, GEMM_SMEM>>>(
            pah, pal, pbh, pbl, nullptr, pzx, DPROJ, DM);

        {
            size_t n = (size_t)(ROWS / 4) * CONVD;
            conv_silu_kernel<<<(unsigned)((n + 255) / 256), 256>>>(
                conv_w + (size_t)l * CONVD * DCONV, conv_b + (size_t)l * CONVD);
        }
        dt_kernel<<<(ROWS * NH + 255) / 256, 256>>>(dt_bias + (size_t)l * NH,
                                                    A_log + (size_t)l * NH);
        scan_kernel<<<BATCH * NH, 256, SCAN_SMEM>>>(Dvec + (size_t)l * NH);
        gate_norm_split_kernel<<<ROWS, 256>>>(gate_w + (size_t)l * DI, pah, pal);

        wsplit_kernel<<<dim3(DM / 32, DI / 32), dim3(32, 8)>>>(
            W_out + (size_t)l * DI * DM, pbh, pbl, DI, DM, DM);
        gemm3_kernel<<<dim3(DM / 128, ROWS / 128), 256, GEMM_SMEM>>>(
            pah, pal, pbh, pbl, hsrc, ph, DM, DI);
    }

    rmsnorm_kernel<<<ROWS, 256>>>(ph, final_w, (float*)d_out, DM);
}

// round 15
// speedup vs baseline: 1.2203x; 1.1277x over previous
#include <cuda_runtime.h>
#include <cuda_bf16.h>
#include <cstdint>

// ---------------- problem constants ----------------
#define BATCH   4
#define SEQL    2048
#define DM      1024
#define DI      2048
#define NH      64
#define HP      32
#define DS      128
#define DCONV   4
#define CONVD   2304            // DI + 2*DS
#define DPROJ   4416            // 2*DI + 2*DS + NH
#define NL      4
#define ROWS    (BATCH*SEQL)    // 8192
#define DT_OFF  (DI + CONVD)    // 4352
#define NPAD_IN 4480            // DPROJ padded to 128 multiple

// ---------------- device scratch (no allocation allowed) ----------------
__device__ float g_h  [(size_t)ROWS * DM];
__device__ float g_zx [(size_t)ROWS * DPROJ];
__device__ float g_xbc[(size_t)ROWS * CONVD];
__device__ float2 g_dd[(size_t)ROWS * NH];     // (dt, dA) packed
__device__ float g_y  [(size_t)ROWS * DI];
// bf16 hi/lo GEMM operands
__device__ __nv_bfloat16 g_ah[(size_t)ROWS * DI];
__device__ __nv_bfloat16 g_al[(size_t)ROWS * DI];
__device__ __nv_bfloat16 g_bh[(size_t)NPAD_IN * 1024];
__device__ __nv_bfloat16 g_bl[(size_t)NPAD_IN * 1024];

// ---------------- small helpers ----------------
__device__ __forceinline__ float silu_f(float v) { return v / (1.0f + expf(-v)); }

__device__ __forceinline__ float block_reduce_sum(float v) {
    __shared__ float red[32];
    int lane = threadIdx.x & 31, wid = threadIdx.x >> 5;
#pragma unroll
    for (int o = 16; o; o >>= 1) v += __shfl_xor_sync(0xffffffffu, v, o);
    if (lane == 0) red[wid] = v;
    __syncthreads();
    float t = (threadIdx.x < (blockDim.x >> 5)) ? red[threadIdx.x] : 0.f;
    if (wid == 0) {
#pragma unroll
        for (int o = 16; o; o >>= 1) t += __shfl_xor_sync(0xffffffffu, t, o);
        if (lane == 0) red[0] = t;
    }
    __syncthreads();
    return red[0];
}

// ---------------- PTX wrappers (sm_100-baseline safe) ----------------
__device__ __forceinline__ uint32_t smem_u32(const void* p) {
    uint32_t a;
    asm("{ .reg .u64 t; cvta.to.shared.u64 t, %1; cvt.u32.u64 %0, t; }" : "=r"(a) : "l"(p));
    return a;
}
__device__ __forceinline__ void cp_async16(uint32_t dst, const void* src) {
    asm volatile("cp.async.cg.shared.global [%0], [%1], 16;" :: "r"(dst), "l"(src));
}
__device__ __forceinline__ void cp_async8(uint32_t dst, const void* src) {
    asm volatile("cp.async.ca.shared.global [%0], [%1], 8;" :: "r"(dst), "l"(src));
}
__device__ __forceinline__ void cp_commit() { asm volatile("cp.async.commit_group;" ::: "memory"); }
__device__ __forceinline__ void cp_wait0()  { asm volatile("cp.async.wait_group 0;" ::: "memory"); }
__device__ __forceinline__ void cp_wait1()  { asm volatile("cp.async.wait_group 1;" ::: "memory"); }

__device__ __forceinline__ void ldm_x4(uint32_t& r0, uint32_t& r1, uint32_t& r2, uint32_t& r3,
                                       uint32_t addr) {
    asm volatile("ldmatrix.sync.aligned.m8n8.x4.shared.b16 {%0,%1,%2,%3}, [%4];"
                 : "=r"(r0), "=r"(r1), "=r"(r2), "=r"(r3) : "r"(addr));
}
__device__ __forceinline__ void mma_bf16(float* c, const uint32_t* a, const uint32_t* b) {
    asm volatile("mma.sync.aligned.m16n8k16.row.col.f32.bf16.bf16.f32 "
                 "{%0,%1,%2,%3}, {%4,%5,%6,%7}, {%8,%9}, {%0,%1,%2,%3};"
                 : "+f"(c[0]), "+f"(c[1]), "+f"(c[2]), "+f"(c[3])
                 : "r"(a[0]), "r"(a[1]), "r"(a[2]), "r"(a[3]), "r"(b[0]), "r"(b[1]));
}

// -------- bf16 triple-pass GEMM: 2-stage, 2 CTAs/SM, interleaved loads, 1 sync/kc ---
#define LDS 40
#define TILEB (128 * LDS * 2)
#define STAGEB (4 * TILEB)
#define GEMM_SMEM (2 * STAGEB)               // 81920 B -> 2 CTAs/SM

__global__ void __launch_bounds__(256, 2)
gemm3_kernel(const __nv_bfloat16* __restrict__ Ah, const __nv_bfloat16* __restrict__ Al,
             const __nv_bfloat16* __restrict__ Bh, const __nv_bfloat16* __restrict__ Bl,
             const float* __restrict__ Cadd, float* __restrict__ C, int N, int K)
{
    extern __shared__ char smem[];
    const uint32_t sb = smem_u32(smem);
    const int tid = threadIdx.x;
    const int lane = tid & 31, wid = tid >> 5;
    const int wm = wid >> 1, wn = wid & 1;
    const size_t m0 = (size_t)blockIdx.y * 128;
    const size_t n0 = (size_t)blockIdx.x * 128;
    const int KC = K >> 5;

    float acc[2][8][4];
#pragma unroll
    for (int i = 0; i < 2; i++)
#pragma unroll
        for (int j = 0; j < 8; j++)
#pragma unroll
            for (int q = 0; q < 4; q++) acc[i][j][q] = 0.f;

    const __nv_bfloat16* gbase[4] = { Ah, Al, Bh, Bl };
    const int amr = lane & 15, akc = (lane >> 4) << 3;
    const int bnr = (lane & 7) + ((lane >> 4) << 3), bkc = ((lane >> 3) & 1) << 3;

    // issue one 16B cp.async: this thread's chunk j of stage st for k-chunk kc
    auto issue_chunk = [&](int kc, int st, int j) {
        size_t kOff = (size_t)kc << 5;
        int i = tid + (j << 8);
        int t = i >> 9, r = (i >> 2) & 127, c = i & 3;
        size_t row = (t < 2) ? (m0 + r) : (n0 + r);
        const __nv_bfloat16* g = gbase[t] + row * (size_t)K + kOff + (c << 3);
        uint32_t d = sb + st * STAGEB + (uint32_t)t * TILEB + (uint32_t)(r * LDS + (c << 3)) * 2;
        cp_async16(d, g);
    };

    // prologue: stage 0
#pragma unroll
    for (int j = 0; j < 8; j++) issue_chunk(0, 0, j);
    cp_commit();

    for (int kc = 0; kc < KC; kc++) {
        int st = kc & 1;
        cp_wait0();
        __syncthreads();                        // single barrier per kc
        const bool pre = (kc + 1 < KC);

        uint32_t sA = sb + st * STAGEB;
        uint32_t sAh = sA;
        uint32_t sAl = sA + TILEB;
        uint32_t sBh = sA + 2 * TILEB;
        uint32_t sBl = sA + 3 * TILEB;

#pragma unroll
        for (int kk = 0; kk < 2; kk++) {
            uint32_t ah[2][4], al[2][4];
#pragma unroll
            for (int mt = 0; mt < 2; mt++) {
                uint32_t off = (uint32_t)((wm * 32 + mt * 16 + amr) * LDS + kk * 16 + akc) * 2;
                ldm_x4(ah[mt][0], ah[mt][1], ah[mt][2], ah[mt][3], sAh + off);
                ldm_x4(al[mt][0], al[mt][1], al[mt][2], al[mt][3], sAl + off);
            }
#pragma unroll
            for (int nt2 = 0; nt2 < 4; nt2++) {
                uint32_t off = (uint32_t)((wn * 64 + nt2 * 16 + bnr) * LDS + kk * 16 + bkc) * 2;
                uint32_t bh0[2], bh1[2], bl0[2], bl1[2];
                ldm_x4(bh0[0], bh0[1], bh1[0], bh1[1], sBh + off);
                ldm_x4(bl0[0], bl0[1], bl1[0], bl1[1], sBl + off);
                if (pre) issue_chunk(kc + 1, st ^ 1, kk * 4 + nt2);  // overlap LSU w/ tensor
                mma_bf16(acc[0][nt2 * 2],     ah[0], bh0);
                mma_bf16(acc[0][nt2 * 2 + 1], ah[0], bh1);
                mma_bf16(acc[1][nt2 * 2],     ah[1], bh0);
                mma_bf16(acc[1][nt2 * 2 + 1], ah[1], bh1);
                mma_bf16(acc[0][nt2 * 2],     ah[0], bl0);
                mma_bf16(acc[0][nt2 * 2 + 1], ah[0], bl1);
                mma_bf16(acc[1][nt2 * 2],     ah[1], bl0);
                mma_bf16(acc[1][nt2 * 2 + 1], ah[1], bl1);
                mma_bf16(acc[0][nt2 * 2],     al[0], bh0);
                mma_bf16(acc[0][nt2 * 2 + 1], al[0], bh1);
                mma_bf16(acc[1][nt2 * 2],     al[1], bh0);
                mma_bf16(acc[1][nt2 * 2 + 1], al[1], bh1);
            }
        }
        if (pre) cp_commit();
    }

    const int colb = (lane & 3) << 1;
    const int rowb = lane >> 2;
#pragma unroll
    for (int mt = 0; mt < 2; mt++) {
        size_t r0 = m0 + wm * 32 + mt * 16 + rowb;
#pragma unroll
        for (int half = 0; half < 2; half++) {
            size_t r = r0 + half * 8;
            float* crow = C + r * (size_t)N;
            const float* arow = Cadd ? Cadd + r * (size_t)N : nullptr;
#pragma unroll
            for (int nt = 0; nt < 8; nt++) {
                int col = (int)n0 + wn * 64 + nt * 8 + colb;
                if (col < N) {
                    float2 v;
                    v.x = acc[mt][nt][half * 2 + 0];
                    v.y = acc[mt][nt][half * 2 + 1];
                    if (arow) { v.x += arow[col]; v.y += arow[col + 1]; }
                    *(float2*)(crow + col) = v;
                }
            }
        }
    }
}

// ---------------- elementwise / norm kernels ----------------
__global__ void rmsnorm_kernel(const float* __restrict__ src, const float* __restrict__ w,
                               float* __restrict__ dst, int D) {
    int row = blockIdx.x;
    const float* s = src + (size_t)row * D;
    float*       d = dst + (size_t)row * D;
    float ss = 0.f;
    for (int i = threadIdx.x * 4; i < D; i += blockDim.x * 4) {
        float4 v = *(const float4*)(s + i);
        ss += v.x * v.x + v.y * v.y + v.z * v.z + v.w * v.w;
    }
    float scale = rsqrtf(block_reduce_sum(ss) / (float)D + 1e-5f);
    for (int i = threadIdx.x * 4; i < D; i += blockDim.x * 4) {
        float4 v = *(const float4*)(s + i);
        float4 wv = *(const float4*)(w + i);
        float4 o;
        o.x = v.x * scale * wv.x; o.y = v.y * scale * wv.y;
        o.z = v.z * scale * wv.z; o.w = v.w * scale * wv.w;
        *(float4*)(d + i) = o;
    }
}

__global__ void rmsnorm_split_kernel(const float* __restrict__ src, const float* __restrict__ w,
                                     __nv_bfloat16* __restrict__ hi, __nv_bfloat16* __restrict__ lo,
                                     int D) {
    int row = blockIdx.x;
    const float* s = src + (size_t)row * D;
    float ss = 0.f;
    for (int i = threadIdx.x * 4; i < D; i += blockDim.x * 4) {
        float4 v = *(const float4*)(s + i);
        ss += v.x * v.x + v.y * v.y + v.z * v.z + v.w * v.w;
    }
    float scale = rsqrtf(block_reduce_sum(ss) / (float)D + 1e-5f);
    for (int i = threadIdx.x * 4; i < D; i += blockDim.x * 4) {
        float4 v = *(const float4*)(s + i);
        float4 wv = *(const float4*)(w + i);
        float o[4] = { v.x * scale * wv.x, v.y * scale * wv.y,
                       v.z * scale * wv.z, v.w * scale * wv.w };
        __nv_bfloat16 h[4], l[4];
#pragma unroll
        for (int q = 0; q < 4; q++) {
            h[q] = __float2bfloat16(o[q]);
            l[q] = __float2bfloat16(o[q] - __bfloat162float(h[q]));
        }
        *(__nv_bfloat162*)(hi + (size_t)row * D + i)     = __nv_bfloat162(h[0], h[1]);
        *(__nv_bfloat162*)(hi + (size_t)row * D + i + 2) = __nv_bfloat162(h[2], h[3]);
        *(__nv_bfloat162*)(lo + (size_t)row * D + i)     = __nv_bfloat162(l[0], l[1]);
        *(__nv_bfloat162*)(lo + (size_t)row * D + i + 2) = __nv_bfloat162(l[2], l[3]);
    }
}

__global__ void wsplit_kernel(const float* __restrict__ W,
                              __nv_bfloat16* __restrict__ Th, __nv_bfloat16* __restrict__ Tl,
                              int K, int N, int Npad) {
    __shared__ float tile[32][33];
    int nb = blockIdx.x * 32, kb = blockIdx.y * 32;
    int tx = threadIdx.x, ty = threadIdx.y;
#pragma unroll
    for (int j = 0; j < 4; j++) {
        int k = kb + ty + j * 8, n = nb + tx;
        tile[ty + j * 8][tx] = (n < N) ? W[(size_t)k * N + n] : 0.f;
    }
    __syncthreads();
#pragma unroll
    for (int j = 0; j < 4; j++) {
        int n = nb + ty + j * 8, k = kb + tx;
        float v = tile[tx][ty + j * 8];
        __nv_bfloat16 h = __float2bfloat16(v);
        Th[(size_t)n * K + k] = h;
        Tl[(size_t)n * K + k] = __float2bfloat16(v - __bfloat162float(h));
    }
}

// causal depthwise conv1d + SiLU, 4 timesteps per thread (sliding window)
__global__ void conv_silu_kernel(const float* __restrict__ cw, const float* __restrict__ cb) {
    size_t idx = (size_t)blockIdx.x * blockDim.x + threadIdx.x;
    if (idx >= (size_t)(ROWS / 4) * CONVD) return;
    int c = (int)(idx % CONVD);
    size_t r = idx / CONVD;
    int lb = (int)(r % (SEQL / 4));
    size_t b = r / (SEQL / 4);
    int l0 = lb * 4;
    const float* col = g_zx + ((b * SEQL + l0)) * (size_t)DPROJ + DI + c;
    float w0 = cw[c * 4 + 0], w1 = cw[c * 4 + 1], w2 = cw[c * 4 + 2], w3 = cw[c * 4 + 3];
    float cbv = cb[c];
    float v[7];
#pragma unroll
    for (int j = 0; j < 7; j++) {
        int l = l0 + j - 3;
        v[j] = (l >= 0) ? col[(ptrdiff_t)(j - 3) * DPROJ] : 0.f;
    }
    float* out = g_xbc + ((b * SEQL + l0)) * (size_t)CONVD + c;
#pragma unroll
    for (int k = 0; k < 4; k++) {
        float acc = cbv + v[k] * w0 + v[k + 1] * w1 + v[k + 2] * w2 + v[k + 3] * w3;
        out[(size_t)k * CONVD] = silu_f(acc);
    }
}

// dt = softplus(raw + bias); dA = exp(dt*A). packed as float2
__global__ void dt_kernel(const float* __restrict__ dtb, const float* __restrict__ Alog) {
    int idx = blockIdx.x * blockDim.x + threadIdx.x;
    if (idx >= ROWS * NH) return;
    int h = idx & (NH - 1);
    int bl = idx >> 6;
    float x = g_zx[(size_t)bl * DPROJ + DT_OFF + h] + dtb[h];
    float sp = (x > 20.f) ? x : log1pf(expf(x));
    g_dd[idx] = make_float2(sp, expf(sp * (-expf(Alog[h]))));
}

// ---------------- selective scan: warp=n-chunk, lane=p, deferred reduction (R10) ----
#define SCHUNK 32
#define SC_BFL (SCHUNK * 128)
#define SC_XFL (SCHUNK * 32)
#define SCAN_SMEM ((2*SC_BFL*2 + 2*SC_XFL + 2*SCHUNK*2 + SCHUNK*256) * 4)  // 107008 B

__global__ void __launch_bounds__(256) scan_kernel(const float* __restrict__ Dv) {
    extern __shared__ float ss[];
    float* sB = ss;
    float* sC = sB + 2 * SC_BFL;
    float* sX = sC + 2 * SC_BFL;
    float* sD = sX + 2 * SC_XFL;
    float* sP = sD + 2 * SCHUNK * 2;

    const uint32_t aB = smem_u32(sB), aC = smem_u32(sC), aX = smem_u32(sX), aD = smem_u32(sD);

    int bh = blockIdx.x;
    int b = bh >> 6, h = bh & 63;
    int tid = threadIdx.x;
    int w = tid >> 5, lane = tid & 31;

    float s[16];
#pragma unroll
    for (int i = 0; i < 16; i++) s[i] = 0.f;

    float Dh = Dv[h];
    const float*  xb  = g_xbc + (size_t)b * SEQL * CONVD;
    const float2* pdd = g_dd  + (size_t)b * SEQL * NH + h;
    float*        yb  = g_y   + (size_t)b * SEQL * DI + h * HP;

    auto load_chunk = [&](int c, int buf) {
        const float* base = xb + (size_t)c * SCHUNK * CONVD;
#pragma unroll
        for (int j = 0; j < 4; j++) {
            int i = tid + (j << 8);
            int t = i >> 5, cc = i & 31;
            const float* src = base + (size_t)t * CONVD + DI + cc * 4;
            cp_async16(aB + (uint32_t)(buf * SC_BFL + t * 128 + cc * 4) * 4, src);
            cp_async16(aC + (uint32_t)(buf * SC_BFL + t * 128 + cc * 4) * 4, src + DS);
        }
        {
            int t = tid >> 3, cc = tid & 7;
            cp_async16(aX + (uint32_t)(buf * SC_XFL + t * 32 + cc * 4) * 4,
                       base + (size_t)t * CONVD + h * HP + cc * 4);
        }
        if (tid < SCHUNK)
            cp_async8(aD + (uint32_t)(buf * SCHUNK + tid) * 8,
                      pdd + ((size_t)c * SCHUNK + tid) * NH);
        cp_commit();
    };

    const int NCH = SEQL / SCHUNK;
    load_chunk(0, 0);

    int buf = 0;
    for (int c = 0; c < NCH; c++) {
        if (c + 1 < NCH) { load_chunk(c + 1, buf ^ 1); cp_wait1(); }
        else             { cp_wait0(); }
        __syncthreads();

        const float*  pB = sB + buf * SC_BFL + w * 16;
        const float*  pC = sC + buf * SC_BFL + w * 16;
        const float*  pX = sX + buf * SC_XFL;
        const float2* pD = (const float2*)(sD + buf * SCHUNK * 2);

#pragma unroll 4
        for (int tt = 0; tt < SCHUNK; tt++) {
            float2 dd = pD[tt];
            float xv = pX[tt * 32 + lane];
            float Bv[16], Cv[16];
#pragma unroll
            for (int j = 0; j < 4; j++) {
                ((float4*)Bv)[j] = *(const float4*)(pB + tt * 128 + j * 4);
                ((float4*)Cv)[j] = *(const float4*)(pC + tt * 128 + j * 4);
            }
            float dtx = dd.x * xv;
            float a0 = 0.f, a1 = 0.f;
#pragma unroll
            for (int i = 0; i < 16; i += 2) {
                s[i]   = fmaf(s[i],   dd.y, dtx * Bv[i]);
                s[i+1] = fmaf(s[i+1], dd.y, dtx * Bv[i+1]);
                a0 = fmaf(s[i],   Cv[i],   a0);
                a1 = fmaf(s[i+1], Cv[i+1], a1);
            }
            sP[tt * 256 + tid] = a0 + a1;
        }
        __syncthreads();

        size_t tg = (size_t)c * SCHUNK;
#pragma unroll
        for (int q = 0; q < 4; q++) {
            int idx = q * 256 + tid;
            int tt = idx >> 5, p = idx & 31;
            const float* pp = sP + tt * 256 + p;
            float y = pp[0] + pp[32] + pp[64] + pp[96] +
                      pp[128] + pp[160] + pp[192] + pp[224];
            float xv = sX[buf * SC_XFL + tt * 32 + p];
            yb[(tg + tt) * DI + p] = fmaf(Dh, xv, y);
        }
        __syncthreads();
        buf ^= 1;
    }
}

// y' = rmsnorm(y * silu(z)) * gw -> bf16 hi/lo (A operand of out_proj)
__global__ void gate_norm_split_kernel(const float* __restrict__ gw,
                                       __nv_bfloat16* __restrict__ hi,
                                       __nv_bfloat16* __restrict__ lo) {
    int row = blockIdx.x;
    const float* yr = g_y  + (size_t)row * DI;
    const float* zr = g_zx + (size_t)row * DPROJ;
    int base = threadIdx.x * 8;
    float v[8];
    float ss = 0.f;
#pragma unroll
    for (int i = 0; i < 8; i++) {
        float g = yr[base + i] * silu_f(zr[base + i]);
        v[i] = g;
        ss += g * g;
    }
    float scale = rsqrtf(block_reduce_sum(ss) / (float)DI + 1e-5f);
    __nv_bfloat16 h[8], l[8];
#pragma unroll
    for (int i = 0; i < 8; i++) {
        float o = v[i] * scale * gw[base + i];
        h[i] = __float2bfloat16(o);
        l[i] = __float2bfloat16(o - __bfloat162float(h[i]));
    }
#pragma unroll
    for (int i = 0; i < 4; i++) {
        *(__nv_bfloat162*)(hi + (size_t)row * DI + base + i * 2) = __nv_bfloat162(h[i * 2], h[i * 2 + 1]);
        *(__nv_bfloat162*)(lo + (size_t)row * DI + base + i * 2) = __nv_bfloat162(l[i * 2], l[i * 2 + 1]);
    }
}

// ---------------- launch ----------------
extern "C" void kernel_launch(void* const* d_in, const int* in_sizes, int n_in,
                              void* d_out, int out_size) {
    const float* x        = (const float*)d_in[0];
    const float* W_in     = (const float*)d_in[1];
    const float* conv_w   = (const float*)d_in[2];
    const float* conv_b   = (const float*)d_in[3];
    const float* dt_bias  = (const float*)d_in[4];
    const float* A_log    = (const float*)d_in[5];
    const float* Dvec     = (const float*)d_in[6];
    const float* gate_w   = (const float*)d_in[7];
    const float* W_out    = (const float*)d_in[8];
    const float* block_w  = (const float*)d_in[9];
    const float* final_w  = (const float*)d_in[10];

    float *ph, *pzx;
    __nv_bfloat16 *pah, *pal, *pbh, *pbl;
    cudaGetSymbolAddress((void**)&ph,  g_h);
    cudaGetSymbolAddress((void**)&pzx, g_zx);
    cudaGetSymbolAddress((void**)&pah, g_ah);
    cudaGetSymbolAddress((void**)&pal, g_al);
    cudaGetSymbolAddress((void**)&pbh, g_bh);
    cudaGetSymbolAddress((void**)&pbl, g_bl);

    cudaFuncSetAttribute(gemm3_kernel, cudaFuncAttributeMaxDynamicSharedMemorySize, GEMM_SMEM);
    cudaFuncSetAttribute(scan_kernel, cudaFuncAttributeMaxDynamicSharedMemorySize, SCAN_SMEM);

    for (int l = 0; l < NL; l++) {
        const float* hsrc = (l == 0) ? x : ph;
        rmsnorm_split_kernel<<<ROWS, 256>>>(hsrc, block_w + (size_t)l * DM, pah, pal, DM);
        wsplit_kernel<<<dim3(NPAD_IN / 32, DM / 32), dim3(32, 8)>>>(
            W_in + (size_t)l * DM * DPROJ, pbh, pbl, DM, DPROJ, NPAD_IN);
        gemm3_kernel<<<dim3(NPAD_IN / 128, ROWS / 128), 256, GEMM_SMEM>>>(
            pah, pal, pbh, pbl, nullptr, pzx, DPROJ, DM);

        {
            size_t n = (size_t)(ROWS / 4) * CONVD;
            conv_silu_kernel<<<(unsigned)((n + 255) / 256), 256>>>(
                conv_w + (size_t)l * CONVD * DCONV, conv_b + (size_t)l * CONVD);
        }
        dt_kernel<<<(ROWS * NH + 255) / 256, 256>>>(dt_bias + (size_t)l * NH,
                                                    A_log + (size_t)l * NH);
        scan_kernel<<<BATCH * NH, 256, SCAN_SMEM>>>(Dvec + (size_t)l * NH);
        gate_norm_split_kernel<<<ROWS, 256>>>(gate_w + (size_t)l * DI, pah, pal);

        wsplit_kernel<<<dim3(DM / 32, DI / 32), dim3(32, 8)>>>(
            W_out + (size_t)l * DI * DM, pbh, pbl, DI, DM, DM);
        gemm3_kernel<<<dim3(DM / 128, ROWS / 128), 256, GEMM_SMEM>>>(
            pah, pal, pbh, pbl, hsrc, ph, DM, DI);
    }

    rmsnorm_kernel<<<ROWS, 256>>>(ph, final_w, (float*)d_out, DM);
}

// round 16
// speedup vs baseline: 1.2363x; 1.0131x over previous
#include <cuda_runtime.h>
#include <cuda_bf16.h>
#include <cstdint>

// ---------------- problem constants ----------------
#define BATCH   4
#define SEQL    2048
#define DM      1024
#define DI      2048
#define NH      64
#define HP      32
#define DS      128
#define DCONV   4
#define CONVD   2304            // DI + 2*DS
#define DPROJ   4416            // 2*DI + 2*DS + NH
#define NL      4
#define ROWS    (BATCH*SEQL)    // 8192
#define DT_OFF  (DI + CONVD)    // 4352
#define NPAD_IN 4480            // DPROJ padded to 128 multiple

// ---------------- device scratch (no allocation allowed) ----------------
__device__ float g_h  [(size_t)ROWS * DM];
__device__ float g_zx [(size_t)ROWS * DPROJ];
__device__ float g_xbc[(size_t)ROWS * CONVD];
__device__ float2 g_dd[(size_t)ROWS * NH];     // (dt, dA) packed
__device__ float g_y  [(size_t)ROWS * DI];
// bf16 hi/lo GEMM operands
__device__ __nv_bfloat16 g_ah[(size_t)ROWS * DI];
__device__ __nv_bfloat16 g_al[(size_t)ROWS * DI];
__device__ __nv_bfloat16 g_bh[(size_t)NPAD_IN * 1024];
__device__ __nv_bfloat16 g_bl[(size_t)NPAD_IN * 1024];

// ---------------- small helpers ----------------
__device__ __forceinline__ float silu_f(float v) { return v / (1.0f + expf(-v)); }

__device__ __forceinline__ float block_reduce_sum(float v) {
    __shared__ float red[32];
    int lane = threadIdx.x & 31, wid = threadIdx.x >> 5;
#pragma unroll
    for (int o = 16; o; o >>= 1) v += __shfl_xor_sync(0xffffffffu, v, o);
    if (lane == 0) red[wid] = v;
    __syncthreads();
    float t = (threadIdx.x < (blockDim.x >> 5)) ? red[threadIdx.x] : 0.f;
    if (wid == 0) {
#pragma unroll
        for (int o = 16; o; o >>= 1) t += __shfl_xor_sync(0xffffffffu, t, o);
        if (lane == 0) red[0] = t;
    }
    __syncthreads();
    return red[0];
}

// ---------------- PTX wrappers (sm_100-baseline safe) ----------------
__device__ __forceinline__ uint32_t smem_u32(const void* p) {
    uint32_t a;
    asm("{ .reg .u64 t; cvta.to.shared.u64 t, %1; cvt.u32.u64 %0, t; }" : "=r"(a) : "l"(p));
    return a;
}
__device__ __forceinline__ void cp_async16(uint32_t dst, const void* src) {
    asm volatile("cp.async.cg.shared.global [%0], [%1], 16;" :: "r"(dst), "l"(src));
}
__device__ __forceinline__ void cp_async8(uint32_t dst, const void* src) {
    asm volatile("cp.async.ca.shared.global [%0], [%1], 8;" :: "r"(dst), "l"(src));
}
__device__ __forceinline__ void cp_commit() { asm volatile("cp.async.commit_group;" ::: "memory"); }
__device__ __forceinline__ void cp_wait0()  { asm volatile("cp.async.wait_group 0;" ::: "memory"); }
__device__ __forceinline__ void cp_wait1()  { asm volatile("cp.async.wait_group 1;" ::: "memory"); }

__device__ __forceinline__ void ldm_x4(uint32_t& r0, uint32_t& r1, uint32_t& r2, uint32_t& r3,
                                       uint32_t addr) {
    asm volatile("ldmatrix.sync.aligned.m8n8.x4.shared.b16 {%0,%1,%2,%3}, [%4];"
                 : "=r"(r0), "=r"(r1), "=r"(r2), "=r"(r3) : "r"(addr));
}
__device__ __forceinline__ void mma_bf16(float* c, const uint32_t* a, const uint32_t* b) {
    asm volatile("mma.sync.aligned.m16n8k16.row.col.f32.bf16.bf16.f32 "
                 "{%0,%1,%2,%3}, {%4,%5,%6,%7}, {%8,%9}, {%0,%1,%2,%3};"
                 : "+f"(c[0]), "+f"(c[1]), "+f"(c[2]), "+f"(c[3])
                 : "r"(a[0]), "r"(a[1]), "r"(a[2]), "r"(a[3]), "r"(b[0]), "r"(b[1]));
}

// -------- bf16 triple-pass GEMM: 2-stage, 2 CTAs/SM, interleaved loads, 1 sync/kc ---
#define LDS 40
#define TILEB (128 * LDS * 2)
#define STAGEB (4 * TILEB)
#define GEMM_SMEM (2 * STAGEB)               // 81920 B -> 2 CTAs/SM

__global__ void __launch_bounds__(256, 2)
gemm3_kernel(const __nv_bfloat16* __restrict__ Ah, const __nv_bfloat16* __restrict__ Al,
             const __nv_bfloat16* __restrict__ Bh, const __nv_bfloat16* __restrict__ Bl,
             const float* __restrict__ Cadd, float* __restrict__ C, int N, int K)
{
    extern __shared__ char smem[];
    const uint32_t sb = smem_u32(smem);
    const int tid = threadIdx.x;
    const int lane = tid & 31, wid = tid >> 5;
    const int wm = wid >> 1, wn = wid & 1;
    const size_t m0 = (size_t)blockIdx.y * 128;
    const size_t n0 = (size_t)blockIdx.x * 128;
    const int KC = K >> 5;

    float acc[2][8][4];
#pragma unroll
    for (int i = 0; i < 2; i++)
#pragma unroll
        for (int j = 0; j < 8; j++)
#pragma unroll
            for (int q = 0; q < 4; q++) acc[i][j][q] = 0.f;

    const __nv_bfloat16* gbase[4] = { Ah, Al, Bh, Bl };
    const int amr = lane & 15, akc = (lane >> 4) << 3;
    const int bnr = (lane & 7) + ((lane >> 4) << 3), bkc = ((lane >> 3) & 1) << 3;

    auto issue_chunk = [&](int kc, int st, int j) {
        size_t kOff = (size_t)kc << 5;
        int i = tid + (j << 8);
        int t = i >> 9, r = (i >> 2) & 127, c = i & 3;
        size_t row = (t < 2) ? (m0 + r) : (n0 + r);
        const __nv_bfloat16* g = gbase[t] + row * (size_t)K + kOff + (c << 3);
        uint32_t d = sb + st * STAGEB + (uint32_t)t * TILEB + (uint32_t)(r * LDS + (c << 3)) * 2;
        cp_async16(d, g);
    };

#pragma unroll
    for (int j = 0; j < 8; j++) issue_chunk(0, 0, j);
    cp_commit();

    for (int kc = 0; kc < KC; kc++) {
        int st = kc & 1;
        cp_wait0();
        __syncthreads();
        const bool pre = (kc + 1 < KC);

        uint32_t sA = sb + st * STAGEB;
        uint32_t sAh = sA;
        uint32_t sAl = sA + TILEB;
        uint32_t sBh = sA + 2 * TILEB;
        uint32_t sBl = sA + 3 * TILEB;

#pragma unroll
        for (int kk = 0; kk < 2; kk++) {
            uint32_t ah[2][4], al[2][4];
#pragma unroll
            for (int mt = 0; mt < 2; mt++) {
                uint32_t off = (uint32_t)((wm * 32 + mt * 16 + amr) * LDS + kk * 16 + akc) * 2;
                ldm_x4(ah[mt][0], ah[mt][1], ah[mt][2], ah[mt][3], sAh + off);
                ldm_x4(al[mt][0], al[mt][1], al[mt][2], al[mt][3], sAl + off);
            }
#pragma unroll
            for (int nt2 = 0; nt2 < 4; nt2++) {
                uint32_t off = (uint32_t)((wn * 64 + nt2 * 16 + bnr) * LDS + kk * 16 + bkc) * 2;
                uint32_t bh0[2], bh1[2], bl0[2], bl1[2];
                ldm_x4(bh0[0], bh0[1], bh1[0], bh1[1], sBh + off);
                ldm_x4(bl0[0], bl0[1], bl1[0], bl1[1], sBl + off);
                if (pre) issue_chunk(kc + 1, st ^ 1, kk * 4 + nt2);
                mma_bf16(acc[0][nt2 * 2],     ah[0], bh0);
                mma_bf16(acc[0][nt2 * 2 + 1], ah[0], bh1);
                mma_bf16(acc[1][nt2 * 2],     ah[1], bh0);
                mma_bf16(acc[1][nt2 * 2 + 1], ah[1], bh1);
                mma_bf16(acc[0][nt2 * 2],     ah[0], bl0);
                mma_bf16(acc[0][nt2 * 2 + 1], ah[0], bl1);
                mma_bf16(acc[1][nt2 * 2],     ah[1], bl0);
                mma_bf16(acc[1][nt2 * 2 + 1], ah[1], bl1);
                mma_bf16(acc[0][nt2 * 2],     al[0], bh0);
                mma_bf16(acc[0][nt2 * 2 + 1], al[0], bh1);
                mma_bf16(acc[1][nt2 * 2],     al[1], bh0);
                mma_bf16(acc[1][nt2 * 2 + 1], al[1], bh1);
            }
        }
        if (pre) cp_commit();
    }

    const int colb = (lane & 3) << 1;
    const int rowb = lane >> 2;
#pragma unroll
    for (int mt = 0; mt < 2; mt++) {
        size_t r0 = m0 + wm * 32 + mt * 16 + rowb;
#pragma unroll
        for (int half = 0; half < 2; half++) {
            size_t r = r0 + half * 8;
            float* crow = C + r * (size_t)N;
            const float* arow = Cadd ? Cadd + r * (size_t)N : nullptr;
#pragma unroll
            for (int nt = 0; nt < 8; nt++) {
                int col = (int)n0 + wn * 64 + nt * 8 + colb;
                if (col < N) {
                    float2 v;
                    v.x = acc[mt][nt][half * 2 + 0];
                    v.y = acc[mt][nt][half * 2 + 1];
                    if (arow) { v.x += arow[col]; v.y += arow[col + 1]; }
                    *(float2*)(crow + col) = v;
                }
            }
        }
    }
}

// ---------------- elementwise / norm kernels ----------------
__global__ void rmsnorm_kernel(const float* __restrict__ src, const float* __restrict__ w,
                               float* __restrict__ dst, int D) {
    int row = blockIdx.x;
    const float* s = src + (size_t)row * D;
    float*       d = dst + (size_t)row * D;
    float ss = 0.f;
    for (int i = threadIdx.x * 4; i < D; i += blockDim.x * 4) {
        float4 v = *(const float4*)(s + i);
        ss += v.x * v.x + v.y * v.y + v.z * v.z + v.w * v.w;
    }
    float scale = rsqrtf(block_reduce_sum(ss) / (float)D + 1e-5f);
    for (int i = threadIdx.x * 4; i < D; i += blockDim.x * 4) {
        float4 v = *(const float4*)(s + i);
        float4 wv = *(const float4*)(w + i);
        float4 o;
        o.x = v.x * scale * wv.x; o.y = v.y * scale * wv.y;
        o.z = v.z * scale * wv.z; o.w = v.w * scale * wv.w;
        *(float4*)(d + i) = o;
    }
}

__global__ void rmsnorm_split_kernel(const float* __restrict__ src, const float* __restrict__ w,
                                     __nv_bfloat16* __restrict__ hi, __nv_bfloat16* __restrict__ lo,
                                     int D) {
    int row = blockIdx.x;
    const float* s = src + (size_t)row * D;
    float ss = 0.f;
    for (int i = threadIdx.x * 4; i < D; i += blockDim.x * 4) {
        float4 v = *(const float4*)(s + i);
        ss += v.x * v.x + v.y * v.y + v.z * v.z + v.w * v.w;
    }
    float scale = rsqrtf(block_reduce_sum(ss) / (float)D + 1e-5f);
    for (int i = threadIdx.x * 4; i < D; i += blockDim.x * 4) {
        float4 v = *(const float4*)(s + i);
        float4 wv = *(const float4*)(w + i);
        float o[4] = { v.x * scale * wv.x, v.y * scale * wv.y,
                       v.z * scale * wv.z, v.w * scale * wv.w };
        __nv_bfloat16 h[4], l[4];
#pragma unroll
        for (int q = 0; q < 4; q++) {
            h[q] = __float2bfloat16(o[q]);
            l[q] = __float2bfloat16(o[q] - __bfloat162float(h[q]));
        }
        *(__nv_bfloat162*)(hi + (size_t)row * D + i)     = __nv_bfloat162(h[0], h[1]);
        *(__nv_bfloat162*)(hi + (size_t)row * D + i + 2) = __nv_bfloat162(h[2], h[3]);
        *(__nv_bfloat162*)(lo + (size_t)row * D + i)     = __nv_bfloat162(l[0], l[1]);
        *(__nv_bfloat162*)(lo + (size_t)row * D + i + 2) = __nv_bfloat162(l[2], l[3]);
    }
}

__global__ void wsplit_kernel(const float* __restrict__ W,
                              __nv_bfloat16* __restrict__ Th, __nv_bfloat16* __restrict__ Tl,
                              int K, int N, int Npad) {
    __shared__ float tile[32][33];
    int nb = blockIdx.x * 32, kb = blockIdx.y * 32;
    int tx = threadIdx.x, ty = threadIdx.y;
#pragma unroll
    for (int j = 0; j < 4; j++) {
        int k = kb + ty + j * 8, n = nb + tx;
        tile[ty + j * 8][tx] = (n < N) ? W[(size_t)k * N + n] : 0.f;
    }
    __syncthreads();
#pragma unroll
    for (int j = 0; j < 4; j++) {
        int n = nb + ty + j * 8, k = kb + tx;
        float v = tile[tx][ty + j * 8];
        __nv_bfloat16 h = __float2bfloat16(v);
        Th[(size_t)n * K + k] = h;
        Tl[(size_t)n * K + k] = __float2bfloat16(v - __bfloat162float(h));
    }
}

// fused: causal depthwise conv1d + SiLU (xBC) AND dt/dA precompute
#define CONV_ITEMS ((size_t)(ROWS / 4) * CONVD)
#define DT_ITEMS   ((size_t)ROWS * NH)
__global__ void conv_dt_kernel(const float* __restrict__ cw, const float* __restrict__ cb,
                               const float* __restrict__ dtb, const float* __restrict__ Alog) {
    size_t idx = (size_t)blockIdx.x * blockDim.x + threadIdx.x;
    if (idx < CONV_ITEMS) {
        int c = (int)(idx % CONVD);
        size_t r = idx / CONVD;
        int lb = (int)(r % (SEQL / 4));
        size_t b = r / (SEQL / 4);
        int l0 = lb * 4;
        const float* col = g_zx + ((b * SEQL + l0)) * (size_t)DPROJ + DI + c;
        float w0 = cw[c * 4 + 0], w1 = cw[c * 4 + 1], w2 = cw[c * 4 + 2], w3 = cw[c * 4 + 3];
        float cbv = cb[c];
        float v[7];
#pragma unroll
        for (int j = 0; j < 7; j++) {
            int l = l0 + j - 3;
            v[j] = (l >= 0) ? col[(ptrdiff_t)(j - 3) * DPROJ] : 0.f;
        }
        float* out = g_xbc + ((b * SEQL + l0)) * (size_t)CONVD + c;
#pragma unroll
        for (int k = 0; k < 4; k++) {
            float acc = cbv + v[k] * w0 + v[k + 1] * w1 + v[k + 2] * w2 + v[k + 3] * w3;
            out[(size_t)k * CONVD] = silu_f(acc);
        }
    } else {
        size_t di = idx - CONV_ITEMS;
        if (di >= DT_ITEMS) return;
        int h = (int)(di & (NH - 1));
        size_t bl = di >> 6;
        float x = g_zx[bl * DPROJ + DT_OFF + h] + dtb[h];
        float sp = (x > 20.f) ? x : log1pf(expf(x));
        g_dd[di] = make_float2(sp, expf(sp * (-expf(Alog[h]))));
    }
}

// ---------------- selective scan: warp=n-chunk, lane=p, deferred reduction (R10) ----
#define SCHUNK 32
#define SC_BFL (SCHUNK * 128)
#define SC_XFL (SCHUNK * 32)
#define SCAN_SMEM ((2*SC_BFL*2 + 2*SC_XFL + 2*SCHUNK*2 + SCHUNK*256) * 4)  // 107008 B

__global__ void __launch_bounds__(256) scan_kernel(const float* __restrict__ Dv) {
    extern __shared__ float ss[];
    float* sB = ss;
    float* sC = sB + 2 * SC_BFL;
    float* sX = sC + 2 * SC_BFL;
    float* sD = sX + 2 * SC_XFL;
    float* sP = sD + 2 * SCHUNK * 2;

    const uint32_t aB = smem_u32(sB), aC = smem_u32(sC), aX = smem_u32(sX), aD = smem_u32(sD);

    int bh = blockIdx.x;
    int b = bh >> 6, h = bh & 63;
    int tid = threadIdx.x;
    int w = tid >> 5, lane = tid & 31;

    float s[16];
#pragma unroll
    for (int i = 0; i < 16; i++) s[i] = 0.f;

    float Dh = Dv[h];
    const float*  xb  = g_xbc + (size_t)b * SEQL * CONVD;
    const float2* pdd = g_dd  + (size_t)b * SEQL * NH + h;
    float*        yb  = g_y   + (size_t)b * SEQL * DI + h * HP;

    auto load_chunk = [&](int c, int buf) {
        const float* base = xb + (size_t)c * SCHUNK * CONVD;
#pragma unroll
        for (int j = 0; j < 4; j++) {
            int i = tid + (j << 8);
            int t = i >> 5, cc = i & 31;
            const float* src = base + (size_t)t * CONVD + DI + cc * 4;
            cp_async16(aB + (uint32_t)(buf * SC_BFL + t * 128 + cc * 4) * 4, src);
            cp_async16(aC + (uint32_t)(buf * SC_BFL + t * 128 + cc * 4) * 4, src + DS);
        }
        {
            int t = tid >> 3, cc = tid & 7;
            cp_async16(aX + (uint32_t)(buf * SC_XFL + t * 32 + cc * 4) * 4,
                       base + (size_t)t * CONVD + h * HP + cc * 4);
        }
        if (tid < SCHUNK)
            cp_async8(aD + (uint32_t)(buf * SCHUNK + tid) * 8,
                      pdd + ((size_t)c * SCHUNK + tid) * NH);
        cp_commit();
    };

    const int NCH = SEQL / SCHUNK;
    load_chunk(0, 0);

    int buf = 0;
    for (int c = 0; c < NCH; c++) {
        if (c + 1 < NCH) { load_chunk(c + 1, buf ^ 1); cp_wait1(); }
        else             { cp_wait0(); }
        __syncthreads();

        const float*  pB = sB + buf * SC_BFL + w * 16;
        const float*  pC = sC + buf * SC_BFL + w * 16;
        const float*  pX = sX + buf * SC_XFL;
        const float2* pD = (const float2*)(sD + buf * SCHUNK * 2);

#pragma unroll 4
        for (int tt = 0; tt < SCHUNK; tt++) {
            float2 dd = pD[tt];
            float xv = pX[tt * 32 + lane];
            float Bv[16], Cv[16];
#pragma unroll
            for (int j = 0; j < 4; j++) {
                ((float4*)Bv)[j] = *(const float4*)(pB + tt * 128 + j * 4);
                ((float4*)Cv)[j] = *(const float4*)(pC + tt * 128 + j * 4);
            }
            float dtx = dd.x * xv;
            float a0 = 0.f, a1 = 0.f;
#pragma unroll
            for (int i = 0; i < 16; i += 2) {
                s[i]   = fmaf(s[i],   dd.y, dtx * Bv[i]);
                s[i+1] = fmaf(s[i+1], dd.y, dtx * Bv[i+1]);
                a0 = fmaf(s[i],   Cv[i],   a0);
                a1 = fmaf(s[i+1], Cv[i+1], a1);
            }
            sP[tt * 256 + tid] = a0 + a1;
        }
        __syncthreads();

        size_t tg = (size_t)c * SCHUNK;
#pragma unroll
        for (int q = 0; q < 4; q++) {
            int idx = q * 256 + tid;
            int tt = idx >> 5, p = idx & 31;
            const float* pp = sP + tt * 256 + p;
            float y = pp[0] + pp[32] + pp[64] + pp[96] +
                      pp[128] + pp[160] + pp[192] + pp[224];
            float xv = sX[buf * SC_XFL + tt * 32 + p];
            yb[(tg + tt) * DI + p] = fmaf(Dh, xv, y);
        }
        __syncthreads();
        buf ^= 1;
    }
}

// y' = rmsnorm(y * silu(z)) * gw -> bf16 hi/lo (A operand of out_proj)
__global__ void gate_norm_split_kernel(const float* __restrict__ gw,
                                       __nv_bfloat16* __restrict__ hi,
                                       __nv_bfloat16* __restrict__ lo) {
    int row = blockIdx.x;
    const float* yr = g_y  + (size_t)row * DI;
    const float* zr = g_zx + (size_t)row * DPROJ;
    int base = threadIdx.x * 8;
    float v[8];
    float ss = 0.f;
#pragma unroll
    for (int q = 0; q < 2; q++) {
        float4 yv = *(const float4*)(yr + base + q * 4);
        float4 zv = *(const float4*)(zr + base + q * 4);
        float g0 = yv.x * silu_f(zv.x);
        float g1 = yv.y * silu_f(zv.y);
        float g2 = yv.z * silu_f(zv.z);
        float g3 = yv.w * silu_f(zv.w);
        v[q * 4 + 0] = g0; v[q * 4 + 1] = g1; v[q * 4 + 2] = g2; v[q * 4 + 3] = g3;
        ss += g0 * g0 + g1 * g1 + g2 * g2 + g3 * g3;
    }
    float scale = rsqrtf(block_reduce_sum(ss) / (float)DI + 1e-5f);
    __nv_bfloat16 h[8], l[8];
#pragma unroll
    for (int i = 0; i < 8; i++) {
        float o = v[i] * scale * gw[base + i];
        h[i] = __float2bfloat16(o);
        l[i] = __float2bfloat16(o - __bfloat162float(h[i]));
    }
#pragma unroll
    for (int i = 0; i < 4; i++) {
        *(__nv_bfloat162*)(hi + (size_t)row * DI + base + i * 2) = __nv_bfloat162(h[i * 2], h[i * 2 + 1]);
        *(__nv_bfloat162*)(lo + (size_t)row * DI + base + i * 2) = __nv_bfloat162(l[i * 2], l[i * 2 + 1]);
    }
}

// ---------------- launch ----------------
extern "C" void kernel_launch(void* const* d_in, const int* in_sizes, int n_in,
                              void* d_out, int out_size) {
    const float* x        = (const float*)d_in[0];
    const float* W_in     = (const float*)d_in[1];
    const float* conv_w   = (const float*)d_in[2];
    const float* conv_b   = (const float*)d_in[3];
    const float* dt_bias  = (const float*)d_in[4];
    const float* A_log    = (const float*)d_in[5];
    const float* Dvec     = (const float*)d_in[6];
    const float* gate_w   = (const float*)d_in[7];
    const float* W_out    = (const float*)d_in[8];
    const float* block_w  = (const float*)d_in[9];
    const float* final_w  = (const float*)d_in[10];

    float *ph, *pzx;
    __nv_bfloat16 *pah, *pal, *pbh, *pbl;
    cudaGetSymbolAddress((void**)&ph,  g_h);
    cudaGetSymbolAddress((void**)&pzx, g_zx);
    cudaGetSymbolAddress((void**)&pah, g_ah);
    cudaGetSymbolAddress((void**)&pal, g_al);
    cudaGetSymbolAddress((void**)&pbh, g_bh);
    cudaGetSymbolAddress((void**)&pbl, g_bl);

    cudaFuncSetAttribute(gemm3_kernel, cudaFuncAttributeMaxDynamicSharedMemorySize, GEMM_SMEM);
    cudaFuncSetAttribute(scan_kernel, cudaFuncAttributeMaxDynamicSharedMemorySize, SCAN_SMEM);

    for (int l = 0; l < NL; l++) {
        const float* hsrc = (l == 0) ? x : ph;
        rmsnorm_split_kernel<<<ROWS, 256>>>(hsrc, block_w + (size_t)l * DM, pah, pal, DM);
        wsplit_kernel<<<dim3(NPAD_IN / 32, DM / 32), dim3(32, 8)>>>(
            W_in + (size_t)l * DM * DPROJ, pbh, pbl, DM, DPROJ, NPAD_IN);
        gemm3_kernel<<<dim3(NPAD_IN / 128, ROWS / 128), 256, GEMM_SMEM>>>(
            pah, pal, pbh, pbl, nullptr, pzx, DPROJ, DM);

        {
            size_t n = CONV_ITEMS + DT_ITEMS;
            conv_dt_kernel<<<(unsigned)((n + 255) / 256), 256>>>(
                conv_w + (size_t)l * CONVD * DCONV, conv_b + (size_t)l * CONVD,
                dt_bias + (size_t)l * NH, A_log + (size_t)l * NH);
        }
        scan_kernel<<<BATCH * NH, 256, SCAN_SMEM>>>(Dvec + (size_t)l * NH);
        gate_norm_split_kernel<<<ROWS, 256>>>(gate_w + (size_t)l * DI, pah, pal);

        wsplit_kernel<<<dim3(DM / 32, DI / 32), dim3(32, 8)>>>(
            W_out + (size_t)l * DI * DM, pbh, pbl, DI, DM, DM);
        gemm3_kernel<<<dim3(DM / 128, ROWS / 128), 256, GEMM_SMEM>>>(
            pah, pal, pbh, pbl, hsrc, ph, DM, DI);
    }

    rmsnorm_kernel<<<ROWS, 256>>>(ph, final_w, (float*)d_out, DM);
}

// round 17
// speedup vs baseline: 1.2421x; 1.0047x over previous
#include <cuda_runtime.h>
#include <cuda_bf16.h>
#include <cstdint>

// ---------------- problem constants ----------------
#define BATCH   4
#define SEQL    2048
#define DM      1024
#define DI      2048
#define NH      64
#define HP      32
#define DS      128
#define DCONV   4
#define CONVD   2304            // DI + 2*DS
#define DPROJ   4416            // 2*DI + 2*DS + NH
#define NL      4
#define ROWS    (BATCH*SEQL)    // 8192
#define DT_OFF  (DI + CONVD)    // 4352
#define NPAD_IN 4480            // DPROJ padded to 128 multiple

// ---------------- device scratch (no allocation allowed) ----------------
__device__ float g_h  [(size_t)ROWS * DM];
__device__ float g_zx [(size_t)ROWS * DPROJ];
__device__ float g_xbc[(size_t)ROWS * CONVD];
__device__ float2 g_dd[(size_t)ROWS * NH];     // (dt, dA) packed
__device__ float g_y  [(size_t)ROWS * DI];
// bf16 hi/lo GEMM operands
__device__ __nv_bfloat16 g_ah [(size_t)ROWS * DI];
__device__ __nv_bfloat16 g_al [(size_t)ROWS * DI];
__device__ __nv_bfloat16 g_bh [(size_t)NPAD_IN * 1024];   // W_in^T split
__device__ __nv_bfloat16 g_bl [(size_t)NPAD_IN * 1024];
__device__ __nv_bfloat16 g_bh2[(size_t)DM * DI];          // W_out^T split
__device__ __nv_bfloat16 g_bl2[(size_t)DM * DI];

// ---------------- small helpers ----------------
__device__ __forceinline__ float silu_f(float v) { return v / (1.0f + expf(-v)); }

__device__ __forceinline__ float block_reduce_sum(float v) {
    __shared__ float red[32];
    int lane = threadIdx.x & 31, wid = threadIdx.x >> 5;
#pragma unroll
    for (int o = 16; o; o >>= 1) v += __shfl_xor_sync(0xffffffffu, v, o);
    if (lane == 0) red[wid] = v;
    __syncthreads();
    float t = (threadIdx.x < (blockDim.x >> 5)) ? red[threadIdx.x] : 0.f;
    if (wid == 0) {
#pragma unroll
        for (int o = 16; o; o >>= 1) t += __shfl_xor_sync(0xffffffffu, t, o);
        if (lane == 0) red[0] = t;
    }
    __syncthreads();
    return red[0];
}

// ---------------- PTX wrappers (sm_100-baseline safe) ----------------
__device__ __forceinline__ uint32_t smem_u32(const void* p) {
    uint32_t a;
    asm("{ .reg .u64 t; cvta.to.shared.u64 t, %1; cvt.u32.u64 %0, t; }" : "=r"(a) : "l"(p));
    return a;
}
__device__ __forceinline__ void cp_async16(uint32_t dst, const void* src) {
    asm volatile("cp.async.cg.shared.global [%0], [%1], 16;" :: "r"(dst), "l"(src));
}
__device__ __forceinline__ void cp_async8(uint32_t dst, const void* src) {
    asm volatile("cp.async.ca.shared.global [%0], [%1], 8;" :: "r"(dst), "l"(src));
}
__device__ __forceinline__ void cp_commit() { asm volatile("cp.async.commit_group;" ::: "memory"); }
__device__ __forceinline__ void cp_wait0()  { asm volatile("cp.async.wait_group 0;" ::: "memory"); }
__device__ __forceinline__ void cp_wait1()  { asm volatile("cp.async.wait_group 1;" ::: "memory"); }

__device__ __forceinline__ void ldm_x4(uint32_t& r0, uint32_t& r1, uint32_t& r2, uint32_t& r3,
                                       uint32_t addr) {
    asm volatile("ldmatrix.sync.aligned.m8n8.x4.shared.b16 {%0,%1,%2,%3}, [%4];"
                 : "=r"(r0), "=r"(r1), "=r"(r2), "=r"(r3) : "r"(addr));
}
__device__ __forceinline__ void mma_bf16(float* c, const uint32_t* a, const uint32_t* b) {
    asm volatile("mma.sync.aligned.m16n8k16.row.col.f32.bf16.bf16.f32 "
                 "{%0,%1,%2,%3}, {%4,%5,%6,%7}, {%8,%9}, {%0,%1,%2,%3};"
                 : "+f"(c[0]), "+f"(c[1]), "+f"(c[2]), "+f"(c[3])
                 : "r"(a[0]), "r"(a[1]), "r"(a[2]), "r"(a[3]), "r"(b[0]), "r"(b[1]));
}

// -------- bf16 triple-pass GEMM: 2-stage, 2 CTAs/SM, interleaved loads, 1 sync/kc ---
#define LDS 40
#define TILEB (128 * LDS * 2)
#define STAGEB (4 * TILEB)
#define GEMM_SMEM (2 * STAGEB)               // 81920 B -> 2 CTAs/SM

__global__ void __launch_bounds__(256, 2)
gemm3_kernel(const __nv_bfloat16* __restrict__ Ah, const __nv_bfloat16* __restrict__ Al,
             const __nv_bfloat16* __restrict__ Bh, const __nv_bfloat16* __restrict__ Bl,
             const float* __restrict__ Cadd, float* __restrict__ C, int N, int K)
{
    extern __shared__ char smem[];
    const uint32_t sb = smem_u32(smem);
    const int tid = threadIdx.x;
    const int lane = tid & 31, wid = tid >> 5;
    const int wm = wid >> 1, wn = wid & 1;
    const size_t m0 = (size_t)blockIdx.y * 128;
    const size_t n0 = (size_t)blockIdx.x * 128;
    const int KC = K >> 5;

    float acc[2][8][4];
#pragma unroll
    for (int i = 0; i < 2; i++)
#pragma unroll
        for (int j = 0; j < 8; j++)
#pragma unroll
            for (int q = 0; q < 4; q++) acc[i][j][q] = 0.f;

    const __nv_bfloat16* gbase[4] = { Ah, Al, Bh, Bl };
    const int amr = lane & 15, akc = (lane >> 4) << 3;
    const int bnr = (lane & 7) + ((lane >> 4) << 3), bkc = ((lane >> 3) & 1) << 3;

    auto issue_chunk = [&](int kc, int st, int j) {
        size_t kOff = (size_t)kc << 5;
        int i = tid + (j << 8);
        int t = i >> 9, r = (i >> 2) & 127, c = i & 3;
        size_t row = (t < 2) ? (m0 + r) : (n0 + r);
        const __nv_bfloat16* g = gbase[t] + row * (size_t)K + kOff + (c << 3);
        uint32_t d = sb + st * STAGEB + (uint32_t)t * TILEB + (uint32_t)(r * LDS + (c << 3)) * 2;
        cp_async16(d, g);
    };

#pragma unroll
    for (int j = 0; j < 8; j++) issue_chunk(0, 0, j);
    cp_commit();

    for (int kc = 0; kc < KC; kc++) {
        int st = kc & 1;
        cp_wait0();
        __syncthreads();
        const bool pre = (kc + 1 < KC);

        uint32_t sA = sb + st * STAGEB;
        uint32_t sAh = sA;
        uint32_t sAl = sA + TILEB;
        uint32_t sBh = sA + 2 * TILEB;
        uint32_t sBl = sA + 3 * TILEB;

#pragma unroll
        for (int kk = 0; kk < 2; kk++) {
            uint32_t ah[2][4], al[2][4];
#pragma unroll
            for (int mt = 0; mt < 2; mt++) {
                uint32_t off = (uint32_t)((wm * 32 + mt * 16 + amr) * LDS + kk * 16 + akc) * 2;
                ldm_x4(ah[mt][0], ah[mt][1], ah[mt][2], ah[mt][3], sAh + off);
                ldm_x4(al[mt][0], al[mt][1], al[mt][2], al[mt][3], sAl + off);
            }
#pragma unroll
            for (int nt2 = 0; nt2 < 4; nt2++) {
                uint32_t off = (uint32_t)((wn * 64 + nt2 * 16 + bnr) * LDS + kk * 16 + bkc) * 2;
                uint32_t bh0[2], bh1[2], bl0[2], bl1[2];
                ldm_x4(bh0[0], bh0[1], bh1[0], bh1[1], sBh + off);
                ldm_x4(bl0[0], bl0[1], bl1[0], bl1[1], sBl + off);
                if (pre) issue_chunk(kc + 1, st ^ 1, kk * 4 + nt2);
                mma_bf16(acc[0][nt2 * 2],     ah[0], bh0);
                mma_bf16(acc[0][nt2 * 2 + 1], ah[0], bh1);
                mma_bf16(acc[1][nt2 * 2],     ah[1], bh0);
                mma_bf16(acc[1][nt2 * 2 + 1], ah[1], bh1);
                mma_bf16(acc[0][nt2 * 2],     ah[0], bl0);
                mma_bf16(acc[0][nt2 * 2 + 1], ah[0], bl1);
                mma_bf16(acc[1][nt2 * 2],     ah[1], bl0);
                mma_bf16(acc[1][nt2 * 2 + 1], ah[1], bl1);
                mma_bf16(acc[0][nt2 * 2],     al[0], bh0);
                mma_bf16(acc[0][nt2 * 2 + 1], al[0], bh1);
                mma_bf16(acc[1][nt2 * 2],     al[1], bh0);
                mma_bf16(acc[1][nt2 * 2 + 1], al[1], bh1);
            }
        }
        if (pre) cp_commit();
    }

    const int colb = (lane & 3) << 1;
    const int rowb = lane >> 2;
#pragma unroll
    for (int mt = 0; mt < 2; mt++) {
        size_t r0 = m0 + wm * 32 + mt * 16 + rowb;
#pragma unroll
        for (int half = 0; half < 2; half++) {
            size_t r = r0 + half * 8;
            float* crow = C + r * (size_t)N;
            const float* arow = Cadd ? Cadd + r * (size_t)N : nullptr;
#pragma unroll
            for (int nt = 0; nt < 8; nt++) {
                int col = (int)n0 + wn * 64 + nt * 8 + colb;
                if (col < N) {
                    float2 v;
                    v.x = acc[mt][nt][half * 2 + 0];
                    v.y = acc[mt][nt][half * 2 + 1];
                    if (arow) { v.x += arow[col]; v.y += arow[col + 1]; }
                    *(float2*)(crow + col) = v;
                }
            }
        }
    }
}

// ---------------- fused per-layer prep: rmsnorm_split + wsplit(W_in) + wsplit(W_out)
// block ranges: [0, ROWS) rmsnorm rows; [ROWS, ROWS+4480) W_in tiles; rest W_out tiles
#define WIN_TILES  ((NPAD_IN / 32) * (DM / 32))   // 140*32 = 4480
#define WOUT_TILES ((DM / 32) * (DI / 32))        // 32*64  = 2048
#define PREP_BLOCKS (ROWS + WIN_TILES + WOUT_TILES)

__device__ __forceinline__ void wsplit_body(const float* __restrict__ W,
                                            __nv_bfloat16* __restrict__ Th,
                                            __nv_bfloat16* __restrict__ Tl,
                                            int K, int N, int nb, int kb,
                                            float* tile /*[32][33]*/) {
    int t = threadIdx.x;
    int tx = t & 31, ty = t >> 5;
#pragma unroll
    for (int j = 0; j < 4; j++) {
        int k = kb + ty + j * 8, n = nb + tx;
        tile[(ty + j * 8) * 33 + tx] = (n < N) ? W[(size_t)k * N + n] : 0.f;
    }
    __syncthreads();
#pragma unroll
    for (int j = 0; j < 4; j++) {
        int n = nb + ty + j * 8, k = kb + tx;
        float v = tile[tx * 33 + ty + j * 8];
        __nv_bfloat16 h = __float2bfloat16(v);
        Th[(size_t)n * K + k] = h;
        Tl[(size_t)n * K + k] = __float2bfloat16(v - __bfloat162float(h));
    }
}

__global__ void __launch_bounds__(256) prep_kernel(
    const float* __restrict__ src, const float* __restrict__ w,     // rmsnorm
    const float* __restrict__ Wi, const float* __restrict__ Wo) {
    __shared__ float tile[32 * 33];
    int blk = blockIdx.x;
    if (blk < ROWS) {
        int row = blk;
        const float* s = src + (size_t)row * DM;
        float ss = 0.f;
        for (int i = threadIdx.x * 4; i < DM; i += 1024) {
            float4 v = *(const float4*)(s + i);
            ss += v.x * v.x + v.y * v.y + v.z * v.z + v.w * v.w;
        }
        float scale = rsqrtf(block_reduce_sum(ss) / (float)DM + 1e-5f);
        for (int i = threadIdx.x * 4; i < DM; i += 1024) {
            float4 v = *(const float4*)(s + i);
            float4 wv = *(const float4*)(w + i);
            float o[4] = { v.x * scale * wv.x, v.y * scale * wv.y,
                           v.z * scale * wv.z, v.w * scale * wv.w };
            __nv_bfloat16 h[4], l[4];
#pragma unroll
            for (int q = 0; q < 4; q++) {
                h[q] = __float2bfloat16(o[q]);
                l[q] = __float2bfloat16(o[q] - __bfloat162float(h[q]));
            }
            *(__nv_bfloat162*)(g_ah + (size_t)row * DM + i)     = __nv_bfloat162(h[0], h[1]);
            *(__nv_bfloat162*)(g_ah + (size_t)row * DM + i + 2) = __nv_bfloat162(h[2], h[3]);
            *(__nv_bfloat162*)(g_al + (size_t)row * DM + i)     = __nv_bfloat162(l[0], l[1]);
            *(__nv_bfloat162*)(g_al + (size_t)row * DM + i + 2) = __nv_bfloat162(l[2], l[3]);
        }
    } else if (blk < ROWS + WIN_TILES) {
        int t = blk - ROWS;
        int nb = (t % (NPAD_IN / 32)) * 32, kb = (t / (NPAD_IN / 32)) * 32;
        wsplit_body(Wi, g_bh, g_bl, DM, DPROJ, nb, kb, tile);
    } else {
        int t = blk - ROWS - WIN_TILES;
        int nb = (t % (DM / 32)) * 32, kb = (t / (DM / 32)) * 32;
        wsplit_body(Wo, g_bh2, g_bl2, DI, DM, nb, kb, tile);
    }
}

// ---------------- final rmsnorm (fp32 out) ----------------
__global__ void rmsnorm_kernel(const float* __restrict__ src, const float* __restrict__ w,
                               float* __restrict__ dst, int D) {
    int row = blockIdx.x;
    const float* s = src + (size_t)row * D;
    float*       d = dst + (size_t)row * D;
    float ss = 0.f;
    for (int i = threadIdx.x * 4; i < D; i += blockDim.x * 4) {
        float4 v = *(const float4*)(s + i);
        ss += v.x * v.x + v.y * v.y + v.z * v.z + v.w * v.w;
    }
    float scale = rsqrtf(block_reduce_sum(ss) / (float)D + 1e-5f);
    for (int i = threadIdx.x * 4; i < D; i += blockDim.x * 4) {
        float4 v = *(const float4*)(s + i);
        float4 wv = *(const float4*)(w + i);
        float4 o;
        o.x = v.x * scale * wv.x; o.y = v.y * scale * wv.y;
        o.z = v.z * scale * wv.z; o.w = v.w * scale * wv.w;
        *(float4*)(d + i) = o;
    }
}

// fused: causal depthwise conv1d + SiLU (xBC) AND dt/dA precompute
#define CONV_ITEMS ((size_t)(ROWS / 4) * CONVD)
#define DT_ITEMS   ((size_t)ROWS * NH)
__global__ void conv_dt_kernel(const float* __restrict__ cw, const float* __restrict__ cb,
                               const float* __restrict__ dtb, const float* __restrict__ Alog) {
    size_t idx = (size_t)blockIdx.x * blockDim.x + threadIdx.x;
    if (idx < CONV_ITEMS) {
        int c = (int)(idx % CONVD);
        size_t r = idx / CONVD;
        int lb = (int)(r % (SEQL / 4));
        size_t b = r / (SEQL / 4);
        int l0 = lb * 4;
        const float* col = g_zx + ((b * SEQL + l0)) * (size_t)DPROJ + DI + c;
        float w0 = cw[c * 4 + 0], w1 = cw[c * 4 + 1], w2 = cw[c * 4 + 2], w3 = cw[c * 4 + 3];
        float cbv = cb[c];
        float v[7];
#pragma unroll
        for (int j = 0; j < 7; j++) {
            int l = l0 + j - 3;
            v[j] = (l >= 0) ? col[(ptrdiff_t)(j - 3) * DPROJ] : 0.f;
        }
        float* out = g_xbc + ((b * SEQL + l0)) * (size_t)CONVD + c;
#pragma unroll
        for (int k = 0; k < 4; k++) {
            float acc = cbv + v[k] * w0 + v[k + 1] * w1 + v[k + 2] * w2 + v[k + 3] * w3;
            out[(size_t)k * CONVD] = silu_f(acc);
        }
    } else {
        size_t di = idx - CONV_ITEMS;
        if (di >= DT_ITEMS) return;
        int h = (int)(di & (NH - 1));
        size_t bl = di >> 6;
        float x = g_zx[bl * DPROJ + DT_OFF + h] + dtb[h];
        float sp = (x > 20.f) ? x : log1pf(expf(x));
        g_dd[di] = make_float2(sp, expf(sp * (-expf(Alog[h]))));
    }
}

// ---------------- selective scan: warp=n-chunk, lane=p, deferred reduction ----------
#define SCHUNK 32
#define SC_BFL (SCHUNK * 128)
#define SC_XFL (SCHUNK * 32)
#define SCAN_SMEM ((2*SC_BFL*2 + 2*SC_XFL + 2*SCHUNK*2 + SCHUNK*256) * 4)  // 107008 B

__global__ void __launch_bounds__(256) scan_kernel(const float* __restrict__ Dv) {
    extern __shared__ float ss[];
    float* sB = ss;
    float* sC = sB + 2 * SC_BFL;
    float* sX = sC + 2 * SC_BFL;
    float* sD = sX + 2 * SC_XFL;
    float* sP = sD + 2 * SCHUNK * 2;

    const uint32_t aB = smem_u32(sB), aC = smem_u32(sC), aX = smem_u32(sX), aD = smem_u32(sD);

    int bh = blockIdx.x;
    int b = bh >> 6, h = bh & 63;
    int tid = threadIdx.x;
    int w = tid >> 5, lane = tid & 31;

    float s[16];
#pragma unroll
    for (int i = 0; i < 16; i++) s[i] = 0.f;

    float Dh = Dv[h];
    const float*  xb  = g_xbc + (size_t)b * SEQL * CONVD;
    const float2* pdd = g_dd  + (size_t)b * SEQL * NH + h;
    float*        yb  = g_y   + (size_t)b * SEQL * DI + h * HP;

    auto load_chunk = [&](int c, int buf) {
        const float* base = xb + (size_t)c * SCHUNK * CONVD;
#pragma unroll
        for (int j = 0; j < 4; j++) {
            int i = tid + (j << 8);
            int t = i >> 5, cc = i & 31;
            const float* src = base + (size_t)t * CONVD + DI + cc * 4;
            cp_async16(aB + (uint32_t)(buf * SC_BFL + t * 128 + cc * 4) * 4, src);
            cp_async16(aC + (uint32_t)(buf * SC_BFL + t * 128 + cc * 4) * 4, src + DS);
        }
        {
            int t = tid >> 3, cc = tid & 7;
            cp_async16(aX + (uint32_t)(buf * SC_XFL + t * 32 + cc * 4) * 4,
                       base + (size_t)t * CONVD + h * HP + cc * 4);
        }
        if (tid < SCHUNK)
            cp_async8(aD + (uint32_t)(buf * SCHUNK + tid) * 8,
                      pdd + ((size_t)c * SCHUNK + tid) * NH);
        cp_commit();
    };

    const int NCH = SEQL / SCHUNK;
    load_chunk(0, 0);

    int buf = 0;
    for (int c = 0; c < NCH; c++) {
        if (c + 1 < NCH) { load_chunk(c + 1, buf ^ 1); cp_wait1(); }
        else             { cp_wait0(); }
        __syncthreads();

        const float*  pB = sB + buf * SC_BFL + w * 16;
        const float*  pC = sC + buf * SC_BFL + w * 16;
        const float*  pX = sX + buf * SC_XFL;
        const float2* pD = (const float2*)(sD + buf * SCHUNK * 2);

#pragma unroll 4
        for (int tt = 0; tt < SCHUNK; tt++) {
            float2 dd = pD[tt];
            float xv = pX[tt * 32 + lane];
            float Bv[16], Cv[16];
#pragma unroll
            for (int j = 0; j < 4; j++) {
                ((float4*)Bv)[j] = *(const float4*)(pB + tt * 128 + j * 4);
                ((float4*)Cv)[j] = *(const float4*)(pC + tt * 128 + j * 4);
            }
            float dtx = dd.x * xv;
            float a0 = 0.f, a1 = 0.f;
#pragma unroll
            for (int i = 0; i < 16; i += 2) {
                s[i]   = fmaf(s[i],   dd.y, dtx * Bv[i]);
                s[i+1] = fmaf(s[i+1], dd.y, dtx * Bv[i+1]);
                a0 = fmaf(s[i],   Cv[i],   a0);
                a1 = fmaf(s[i+1], Cv[i+1], a1);
            }
            sP[tt * 256 + tid] = a0 + a1;
        }
        __syncthreads();

        size_t tg = (size_t)c * SCHUNK;
#pragma unroll
        for (int q = 0; q < 4; q++) {
            int idx = q * 256 + tid;
            int tt = idx >> 5, p = idx & 31;
            const float* pp = sP + tt * 256 + p;
            float y = pp[0] + pp[32] + pp[64] + pp[96] +
                      pp[128] + pp[160] + pp[192] + pp[224];
            float xv = sX[buf * SC_XFL + tt * 32 + p];
            yb[(tg + tt) * DI + p] = fmaf(Dh, xv, y);
        }
        __syncthreads();
        buf ^= 1;
    }
}

// y' = rmsnorm(y * silu(z)) * gw -> bf16 hi/lo (A operand of out_proj)
__global__ void gate_norm_split_kernel(const float* __restrict__ gw,
                                       __nv_bfloat16* __restrict__ hi,
                                       __nv_bfloat16* __restrict__ lo) {
    int row = blockIdx.x;
    const float* yr = g_y  + (size_t)row * DI;
    const float* zr = g_zx + (size_t)row * DPROJ;
    int base = threadIdx.x * 8;
    float v[8];
    float ss = 0.f;
#pragma unroll
    for (int q = 0; q < 2; q++) {
        float4 yv = *(const float4*)(yr + base + q * 4);
        float4 zv = *(const float4*)(zr + base + q * 4);
        float g0 = yv.x * silu_f(zv.x);
        float g1 = yv.y * silu_f(zv.y);
        float g2 = yv.z * silu_f(zv.z);
        float g3 = yv.w * silu_f(zv.w);
        v[q * 4 + 0] = g0; v[q * 4 + 1] = g1; v[q * 4 + 2] = g2; v[q * 4 + 3] = g3;
        ss += g0 * g0 + g1 * g1 + g2 * g2 + g3 * g3;
    }
    float scale = rsqrtf(block_reduce_sum(ss) / (float)DI + 1e-5f);
    __nv_bfloat16 h[8], l[8];
#pragma unroll
    for (int i = 0; i < 8; i++) {
        float o = v[i] * scale * gw[base + i];
        h[i] = __float2bfloat16(o);
        l[i] = __float2bfloat16(o - __bfloat162float(h[i]));
    }
#pragma unroll
    for (int i = 0; i < 4; i++) {
        *(__nv_bfloat162*)(hi + (size_t)row * DI + base + i * 2) = __nv_bfloat162(h[i * 2], h[i * 2 + 1]);
        *(__nv_bfloat162*)(lo + (size_t)row * DI + base + i * 2) = __nv_bfloat162(l[i * 2], l[i * 2 + 1]);
    }
}

// ---------------- launch ----------------
extern "C" void kernel_launch(void* const* d_in, const int* in_sizes, int n_in,
                              void* d_out, int out_size) {
    const float* x        = (const float*)d_in[0];
    const float* W_in     = (const float*)d_in[1];
    const float* conv_w   = (const float*)d_in[2];
    const float* conv_b   = (const float*)d_in[3];
    const float* dt_bias  = (const float*)d_in[4];
    const float* A_log    = (const float*)d_in[5];
    const float* Dvec     = (const float*)d_in[6];
    const float* gate_w   = (const float*)d_in[7];
    const float* W_out    = (const float*)d_in[8];
    const float* block_w  = (const float*)d_in[9];
    const float* final_w  = (const float*)d_in[10];

    float *ph, *pzx;
    __nv_bfloat16 *pah, *pal, *pbh, *pbl, *pbh2, *pbl2;
    cudaGetSymbolAddress((void**)&ph,   g_h);
    cudaGetSymbolAddress((void**)&pzx,  g_zx);
    cudaGetSymbolAddress((void**)&pah,  g_ah);
    cudaGetSymbolAddress((void**)&pal,  g_al);
    cudaGetSymbolAddress((void**)&pbh,  g_bh);
    cudaGetSymbolAddress((void**)&pbl,  g_bl);
    cudaGetSymbolAddress((void**)&pbh2, g_bh2);
    cudaGetSymbolAddress((void**)&pbl2, g_bl2);

    cudaFuncSetAttribute(gemm3_kernel, cudaFuncAttributeMaxDynamicSharedMemorySize, GEMM_SMEM);
    cudaFuncSetAttribute(scan_kernel, cudaFuncAttributeMaxDynamicSharedMemorySize, SCAN_SMEM);

    for (int l = 0; l < NL; l++) {
        const float* hsrc = (l == 0) ? x : ph;
        prep_kernel<<<PREP_BLOCKS, 256>>>(hsrc, block_w + (size_t)l * DM,
                                          W_in + (size_t)l * DM * DPROJ,
                                          W_out + (size_t)l * DI * DM);
        gemm3_kernel<<<dim3(NPAD_IN / 128, ROWS / 128), 256, GEMM_SMEM>>>(
            pah, pal, pbh, pbl, nullptr, pzx, DPROJ, DM);

        {
            size_t n = CONV_ITEMS + DT_ITEMS;
            conv_dt_kernel<<<(unsigned)((n + 255) / 256), 256>>>(
                conv_w + (size_t)l * CONVD * DCONV, conv_b + (size_t)l * CONVD,
                dt_bias + (size_t)l * NH, A_log + (size_t)l * NH);
        }
        scan_kernel<<<BATCH * NH, 256, SCAN_SMEM>>>(Dvec + (size_t)l * NH);
        gate_norm_split_kernel<<<ROWS, 256>>>(gate_w + (size_t)l * DI, pah, pal);

        gemm3_kernel<<<dim3(DM / 128, ROWS / 128), 256, GEMM_SMEM>>>(
            pah, pal, pbh2, pbl2, hsrc, ph, DM, DI);
    }

    rmsnorm_kernel<<<ROWS, 256>>>(ph, final_w, (float*)d_out, DM);
}